// round 9
// baseline (speedup 1.0000x reference)
#include <cuda_runtime.h>
#include <cstdint>

#define NN 100000
#define NE 1600000
#define FD 128
#define NG 64
#define NC 32

#define NBLK ((NN + 255) / 256)   // 391 scan blocks

// ---------------- scratch (static device globals; allocation-free) ----------
// g_deg is zero on first use (static init) and re-zeroed by k_cleanup at the
// end of every kernel_launch, keeping graph replays deterministic.
__device__ int    g_deg[NN];
__device__ int    g_offs[NN + 1];
__device__ int    g_cursor[NN];
__device__ float2 g_edge[NE];          // (.x = src idx bitcast, .y = weight)
__device__ float  g_dinv[NN];
__device__ int    g_bsum[NBLK];
__device__ float  g_bufA[(size_t)NN * FD];
__device__ float  g_bufB[(size_t)NN * FD];
__device__ float  g_pooled[NG * FD];

// ---------------- helpers -----------------------------------------------------
__device__ __forceinline__ uint32_t f2tf32(float x) {
    uint32_t r; asm("cvt.rna.tf32.f32 %0, %1;" : "=r"(r) : "f"(x)); return r;
}

__device__ __forceinline__ void mma_tf32(float* d, const uint32_t* a, uint32_t b0, uint32_t b1) {
    asm volatile("mma.sync.aligned.m16n8k8.row.col.f32.tf32.tf32.f32 "
                 "{%0,%1,%2,%3}, {%4,%5,%6,%7}, {%8,%9}, {%0,%1,%2,%3};"
                 : "+f"(d[0]), "+f"(d[1]), "+f"(d[2]), "+f"(d[3])
                 : "r"(a[0]), "r"(a[1]), "r"(a[2]), "r"(a[3]), "r"(b0), "r"(b1));
}

__device__ __forceinline__ void cp_async16(uint32_t saddr, const void* gptr, int src_bytes) {
    asm volatile("cp.async.ca.shared.global [%0], [%1], 16, %2;"
                 :: "r"(saddr), "l"(gptr), "r"(src_bytes));
}

// ---------------- degree histogram ----------------------------------------------
__global__ void k_deg(const int* __restrict__ dst, int ne) {
    int i = blockIdx.x * blockDim.x + threadIdx.x;
    if (i < ne) atomicAdd(&g_deg[dst[i]], 1);
}

// ---------------- block sums ------------------------------------------------------
__global__ void k_blocksum() {
    __shared__ int s[256];
    int i = blockIdx.x * 256 + threadIdx.x;
    s[threadIdx.x] = (i < NN) ? g_deg[i] : 0;
    __syncthreads();
    for (int d = 128; d > 0; d >>= 1) {
        if (threadIdx.x < d) s[threadIdx.x] += s[threadIdx.x + d];
        __syncthreads();
    }
    if (threadIdx.x == 0) g_bsum[blockIdx.x] = s[0];
}

// ---------------- offsets: fused block-prefix + intra-block scan + dinv ----------
__global__ void k_offsets(int ne) {
    __shared__ int red[8];
    __shared__ int warp_sums[8];
    __shared__ int s_prefix;
    int tid = threadIdx.x;

    // exclusive prefix of block sums: sum g_bsum[0..blockIdx.x)
    int p = 0;
    for (int i = tid; i < blockIdx.x; i += 256) p += g_bsum[i];
    #pragma unroll
    for (int d = 16; d; d >>= 1) p += __shfl_down_sync(0xffffffffu, p, d);
    if ((tid & 31) == 0) red[tid >> 5] = p;
    __syncthreads();
    if (tid == 0) {
        int t = 0;
        #pragma unroll
        for (int w = 0; w < 8; w++) t += red[w];
        s_prefix = t;
    }
    __syncthreads();
    int prefix = s_prefix;

    int i = blockIdx.x * 256 + tid;
    int v = (i < NN) ? g_deg[i] : 0;
    int x = v;
    #pragma unroll
    for (int d = 1; d < 32; d <<= 1) {
        int y = __shfl_up_sync(0xffffffffu, x, d);
        if ((tid & 31) >= d) x += y;
    }
    if ((tid & 31) == 31) warp_sums[tid >> 5] = x;
    __syncthreads();
    if (tid < 8) {
        int y = warp_sums[tid];
        #pragma unroll
        for (int d = 1; d < 8; d <<= 1) {
            int z = __shfl_up_sync(0xffu, y, d);
            if (tid >= d) y += z;
        }
        warp_sums[tid] = y;
    }
    __syncthreads();
    int incl = x + ((tid >= 32) ? warp_sums[(tid >> 5) - 1] : 0);
    int excl = incl - v + prefix;
    if (i < NN) {
        g_offs[i] = excl;
        g_cursor[i] = excl;
        g_dinv[i] = rsqrtf((float)v + 1.0f);
    }
    if (blockIdx.x == 0 && tid == 0) g_offs[NN] = ne;
}

// ---------------- CSR scatter with fused edge weight ---------------------------
__global__ void k_scatter(const int* __restrict__ src,
                          const int* __restrict__ dst, int ne) {
    int i = blockIdx.x * blockDim.x + threadIdx.x;
    if (i < ne) {
        int d = dst[i];
        int sN = src[i];
        float w = g_dinv[d] * g_dinv[sN];
        int pos = atomicAdd(&g_cursor[d], 1);
        __stcs(&g_edge[pos], make_float2(__int_as_float(sN), w));
    }
}

// ---------------- tf32 tensor-core GEMM: C[n,128] = A[n,128] @ W[128,128] ------
// Single-term tf32. W resident in smem (converted once); A double-buffered k=32
// chunks via cp.async. Normal C stores (L2-resident for the following agg).
#define WS_STRIDE 136
#define AS_STRIDE 36
#define A_CHUNK_FLOATS (128 * AS_STRIDE)     // 4608 per buffer
#define GEMM_SMEM ((128 * WS_STRIDE + 2 * A_CHUNK_FLOATS) * 4)   // 106,496 B

__global__ __launch_bounds__(256, 2) void k_gemm_tf32(const float* __restrict__ A,
                                                      const float* __restrict__ W,
                                                      float* __restrict__ C, int nrows) {
    extern __shared__ float smem[];
    float* Ws = smem;                         // [128][136] tf32-converted
    float* As = smem + 128 * WS_STRIDE;       // [2][128][36] fp32

    int tid = threadIdx.x;
    int row0 = blockIdx.x * 128;
    uint32_t as_base = (uint32_t)__cvta_generic_to_shared(As);

    for (int i = tid; i < 128 * 32; i += 256) {
        int r = i >> 5, c = i & 31;
        float4 v = ((const float4*)(W + (size_t)r * FD))[c];
        float* d = Ws + r * WS_STRIDE + c * 4;
        d[0] = __uint_as_float(f2tf32(v.x));
        d[1] = __uint_as_float(f2tf32(v.y));
        d[2] = __uint_as_float(f2tf32(v.z));
        d[3] = __uint_as_float(f2tf32(v.w));
    }

    auto load_chunk = [&](int c, int buf) {
        #pragma unroll
        for (int i = 0; i < 4; i++) {
            int idx = tid + i * 256;
            int r = idx >> 3;
            int q = idx & 7;
            const float* g = A + (size_t)(row0 + r) * FD + c * 32 + q * 4;
            uint32_t s = as_base + (uint32_t)(buf * A_CHUNK_FLOATS + r * AS_STRIDE + q * 4) * 4;
            cp_async16(s, g, (row0 + r < nrows) ? 16 : 0);
        }
    };

    int lane = tid & 31;
    int wid  = tid >> 5;
    int wr = wid & 3;
    int wc = wid >> 2;
    int qrow = lane >> 2;
    int qcol = lane & 3;

    float acc[2][8][4];
    #pragma unroll
    for (int s = 0; s < 2; s++)
        #pragma unroll
        for (int t = 0; t < 8; t++)
            #pragma unroll
            for (int q = 0; q < 4; q++) acc[s][t][q] = 0.f;

    load_chunk(0, 0);
    asm volatile("cp.async.commit_group;" ::: "memory");

    #pragma unroll
    for (int c = 0; c < 4; c++) {
        int buf = c & 1;
        if (c < 3) {
            load_chunk(c + 1, buf ^ 1);
            asm volatile("cp.async.commit_group;" ::: "memory");
            asm volatile("cp.async.wait_group 1;" ::: "memory");
        } else {
            asm volatile("cp.async.wait_group 0;" ::: "memory");
        }
        __syncthreads();

        const float* Ab = As + buf * A_CHUNK_FLOATS;
        #pragma unroll
        for (int kk2 = 0; kk2 < 4; kk2++) {
            int k0 = kk2 * 8;
            int K0 = c * 32 + k0;
            uint32_t af[2][4];
            #pragma unroll
            for (int s = 0; s < 2; s++) {
                int rb = 32 * wr + 16 * s + qrow;
                af[s][0] = f2tf32(Ab[(rb)     * AS_STRIDE + k0 + qcol]);
                af[s][1] = f2tf32(Ab[(rb + 8) * AS_STRIDE + k0 + qcol]);
                af[s][2] = f2tf32(Ab[(rb)     * AS_STRIDE + k0 + qcol + 4]);
                af[s][3] = f2tf32(Ab[(rb + 8) * AS_STRIDE + k0 + qcol + 4]);
            }
            #pragma unroll
            for (int t = 0; t < 8; t++) {
                int n = 64 * wc + 8 * t + qrow;
                uint32_t b0 = __float_as_uint(Ws[(K0 + qcol)     * WS_STRIDE + n]);
                uint32_t b1 = __float_as_uint(Ws[(K0 + qcol + 4) * WS_STRIDE + n]);
                mma_tf32(acc[0][t], af[0], b0, b1);
                mma_tf32(acc[1][t], af[1], b0, b1);
            }
        }
        __syncthreads();
    }

    #pragma unroll
    for (int s = 0; s < 2; s++) {
        int rbase = row0 + 32 * wr + 16 * s + qrow;
        #pragma unroll
        for (int t = 0; t < 8; t++) {
            int col = 64 * wc + 8 * t + 2 * qcol;
            if (rbase < nrows)
                *(float2*)(C + (size_t)rbase * FD + col) = make_float2(acc[s][t][0], acc[s][t][1]);
            if (rbase + 8 < nrows)
                *(float2*)(C + (size_t)(rbase + 8) * FD + col) = make_float2(acc[s][t][2], acc[s][t][3]);
        }
    }
}

// ---------------- GCN aggregation: warp/node, clamped 8-wide batches -----------
__global__ void k_agg(const float* __restrict__ h, const float* __restrict__ bias,
                      float* __restrict__ out) {
    int gw = (blockIdx.x * blockDim.x + threadIdx.x) >> 5;
    if (gw >= NN) return;
    int lane = threadIdx.x & 31;
    int s = g_offs[gw], e = g_offs[gw + 1];

    float4 acc0 = make_float4(0.f, 0.f, 0.f, 0.f);
    float4 acc1 = make_float4(0.f, 0.f, 0.f, 0.f);

    for (int j = s; j < e; j += 8) {
        float2 ed[8];
        #pragma unroll
        for (int u = 0; u < 8; u++) {
            int jj = (j + u < e) ? j + u : e - 1;      // clamp (e > s here)
            ed[u] = __ldcs(&g_edge[jj]);
            if (j + u >= e) ed[u].y = 0.f;             // zero weight for tail dups
        }
        float4 v[8];
        #pragma unroll
        for (int u = 0; u < 8; u++)
            v[u] = ((const float4*)(h + (size_t)__float_as_int(ed[u].x) * FD))[lane];
        #pragma unroll
        for (int u = 0; u < 8; u += 2) {
            acc0.x = fmaf(ed[u].y, v[u].x, acc0.x); acc0.y = fmaf(ed[u].y, v[u].y, acc0.y);
            acc0.z = fmaf(ed[u].y, v[u].z, acc0.z); acc0.w = fmaf(ed[u].y, v[u].w, acc0.w);
            acc1.x = fmaf(ed[u+1].y, v[u+1].x, acc1.x); acc1.y = fmaf(ed[u+1].y, v[u+1].y, acc1.y);
            acc1.z = fmaf(ed[u+1].y, v[u+1].z, acc1.z); acc1.w = fmaf(ed[u+1].y, v[u+1].w, acc1.w);
        }
    }
    {   // self loop
        float di = g_dinv[gw];
        float w = di * di;
        float4 v = ((const float4*)(h + (size_t)gw * FD))[lane];
        acc0.x = fmaf(w, v.x, acc0.x); acc0.y = fmaf(w, v.y, acc0.y);
        acc0.z = fmaf(w, v.z, acc0.z); acc0.w = fmaf(w, v.w, acc0.w);
    }
    float4 b4 = ((const float4*)bias)[lane];
    float4 r;
    r.x = fmaxf(acc0.x + acc1.x + b4.x, 0.f);
    r.y = fmaxf(acc0.y + acc1.y + b4.y, 0.f);
    r.z = fmaxf(acc0.z + acc1.z + b4.z, 0.f);
    r.w = fmaxf(acc0.w + acc1.w + b4.w, 0.f);
    __stcs((float4*)(out + (size_t)gw * FD) + lane, r);
}

// ---------------- per-graph mean pool (binary-search boundaries) ---------------
__global__ void k_pool(const float* __restrict__ h, const int* __restrict__ bat) {
    int g = blockIdx.x;
    __shared__ int se[2];
    if (threadIdx.x < 2) {
        int target = g + threadIdx.x;
        int lo = 0, hi = NN;
        while (lo < hi) { int m = (lo + hi) >> 1; if (bat[m] < target) lo = m + 1; else hi = m; }
        se[threadIdx.x] = lo;
    }
    __syncthreads();
    int s = se[0], e = se[1];
    int c = blockIdx.y * 32 + threadIdx.x;   // gridDim.y = 4
    float acc0 = 0.f, acc1 = 0.f, acc2 = 0.f, acc3 = 0.f;
    int i = s;
    for (; i + 4 <= e; i += 4) {
        acc0 += h[(size_t)(i + 0) * FD + c];
        acc1 += h[(size_t)(i + 1) * FD + c];
        acc2 += h[(size_t)(i + 2) * FD + c];
        acc3 += h[(size_t)(i + 3) * FD + c];
    }
    for (; i < e; i++) acc0 += h[(size_t)i * FD + c];
    float cnt = (float)((e - s) > 1 ? (e - s) : 1);
    g_pooled[g * FD + c] = (acc0 + acc1 + acc2 + acc3) / cnt;
}

// ---------------- final FC -------------------------------------------------------
__global__ void k_fc(const float* __restrict__ fcW, const float* __restrict__ fcb,
                     float* __restrict__ out) {
    int g = blockIdx.x;
    int c = threadIdx.x;
    float acc = fcb[c];
    #pragma unroll 4
    for (int k = 0; k < FD; k++)
        acc = fmaf(g_pooled[g * FD + k], fcW[k * NC + c], acc);
    out[g * NC + c] = acc;
}

// ---------------- cleanup: restore zero state for next graph replay -------------
__global__ void k_cleanup() {
    int i = blockIdx.x * blockDim.x + threadIdx.x;
    if (i < NN) g_deg[i] = 0;
}

// ---------------- launch ----------------------------------------------------------
extern "C" void kernel_launch(void* const* d_in, const int* in_sizes, int n_in,
                              void* d_out, int out_size) {
    const float* x    = (const float*)d_in[0];
    const int*   ei   = (const int*)d_in[1];
    const int*   bat  = (const int*)d_in[2];
    const float* W1   = (const float*)d_in[3];
    const float* b1   = (const float*)d_in[4];
    const float* W2   = (const float*)d_in[5];
    const float* b2   = (const float*)d_in[6];
    const float* fcW  = (const float*)d_in[7];
    const float* fcb  = (const float*)d_in[8];
    float* out = (float*)d_out;

    int ne = in_sizes[1] / 2;
    const int* src = ei;
    const int* dst = ei + ne;

    float *bufA, *bufB;
    cudaGetSymbolAddress((void**)&bufA, g_bufA);
    cudaGetSymbolAddress((void**)&bufB, g_bufB);

    cudaFuncSetAttribute(k_gemm_tf32, cudaFuncAttributeMaxDynamicSharedMemorySize, GEMM_SMEM);

    int tb = 256;
    int gbN   = (NN + tb - 1) / tb;
    int gbE   = (ne + tb - 1) / tb;
    int gbAgg = (NN * 32 + tb - 1) / tb;
    int gbGemm = (NN + 127) / 128;

    // launch index 3 (profiled slot) = k_scatter this round
    k_deg<<<gbE, tb>>>(dst, ne);                                    // 0
    k_blocksum<<<NBLK, tb>>>();                                     // 1
    k_offsets<<<NBLK, tb>>>(ne);                                    // 2
    k_scatter<<<gbE, tb>>>(src, dst, ne);                           // 3 <- profiled
    k_gemm_tf32<<<gbGemm, tb, GEMM_SMEM>>>(x, W1, bufA, NN);        // 4
    k_agg<<<gbAgg, tb>>>(bufA, b1, bufB);                           // 5
    k_gemm_tf32<<<gbGemm, tb, GEMM_SMEM>>>(bufB, W2, bufA, NN);     // 6
    k_agg<<<gbAgg, tb>>>(bufA, b2, bufB);                           // 7
    k_pool<<<dim3(NG, 4), 32>>>(bufB, bat);                         // 8
    k_fc<<<NG, NC>>>(fcW, fcb, out);                                // 9
    k_cleanup<<<gbN, tb>>>();                                       // 10
}

// round 10
// speedup vs baseline: 1.0156x; 1.0156x over previous
#include <cuda_runtime.h>
#include <cuda_fp16.h>
#include <cstdint>

#define NN 100000
#define NE 1600000
#define FD 128
#define NG 64
#define NC 32

#define NBLK ((NN + 255) / 256)   // 391 scan blocks

// ---------------- scratch (static device globals; allocation-free) ----------
// g_deg is zero on first use and re-zeroed by k_cleanup every launch (replay-safe).
__device__ int    g_deg[NN];
__device__ int    g_offs[NN + 1];
__device__ int    g_cursor[NN];
__device__ float2 g_edge[NE];          // (.x = src idx bitcast, .y = weight)
__device__ float  g_dinv[NN];
__device__ int    g_bsum[NBLK];
__device__ float  g_bufA[(size_t)NN * FD];    // gemm out fp32
__device__ __half g_bufAh[(size_t)NN * FD];   // gemm out fp16 (gather mirror)
__device__ float  g_bufB[(size_t)NN * FD];    // agg out fp32
__device__ float  g_pooled[NG * FD];

// ---------------- helpers -----------------------------------------------------
__device__ __forceinline__ uint32_t f2tf32(float x) {
    uint32_t r; asm("cvt.rna.tf32.f32 %0, %1;" : "=r"(r) : "f"(x)); return r;
}

__device__ __forceinline__ void mma_tf32(float* d, const uint32_t* a, uint32_t b0, uint32_t b1) {
    asm volatile("mma.sync.aligned.m16n8k8.row.col.f32.tf32.tf32.f32 "
                 "{%0,%1,%2,%3}, {%4,%5,%6,%7}, {%8,%9}, {%0,%1,%2,%3};"
                 : "+f"(d[0]), "+f"(d[1]), "+f"(d[2]), "+f"(d[3])
                 : "r"(a[0]), "r"(a[1]), "r"(a[2]), "r"(a[3]), "r"(b0), "r"(b1));
}

__device__ __forceinline__ void cp_async16(uint32_t saddr, const void* gptr, int src_bytes) {
    asm volatile("cp.async.ca.shared.global [%0], [%1], 16, %2;"
                 :: "r"(saddr), "l"(gptr), "r"(src_bytes));
}

// ---------------- degree histogram ----------------------------------------------
__global__ void k_deg(const int* __restrict__ dst, int ne) {
    int i = blockIdx.x * blockDim.x + threadIdx.x;
    if (i < ne) atomicAdd(&g_deg[dst[i]], 1);
}

// ---------------- block sums ------------------------------------------------------
__global__ void k_blocksum() {
    __shared__ int s[256];
    int i = blockIdx.x * 256 + threadIdx.x;
    s[threadIdx.x] = (i < NN) ? g_deg[i] : 0;
    __syncthreads();
    for (int d = 128; d > 0; d >>= 1) {
        if (threadIdx.x < d) s[threadIdx.x] += s[threadIdx.x + d];
        __syncthreads();
    }
    if (threadIdx.x == 0) g_bsum[blockIdx.x] = s[0];
}

// ---------------- offsets: fused block-prefix + intra-block scan + dinv ----------
__global__ void k_offsets(int ne) {
    __shared__ int red[8];
    __shared__ int warp_sums[8];
    __shared__ int s_prefix;
    int tid = threadIdx.x;

    int p = 0;
    for (int i = tid; i < blockIdx.x; i += 256) p += g_bsum[i];
    #pragma unroll
    for (int d = 16; d; d >>= 1) p += __shfl_down_sync(0xffffffffu, p, d);
    if ((tid & 31) == 0) red[tid >> 5] = p;
    __syncthreads();
    if (tid == 0) {
        int t = 0;
        #pragma unroll
        for (int w = 0; w < 8; w++) t += red[w];
        s_prefix = t;
    }
    __syncthreads();
    int prefix = s_prefix;

    int i = blockIdx.x * 256 + tid;
    int v = (i < NN) ? g_deg[i] : 0;
    int x = v;
    #pragma unroll
    for (int d = 1; d < 32; d <<= 1) {
        int y = __shfl_up_sync(0xffffffffu, x, d);
        if ((tid & 31) >= d) x += y;
    }
    if ((tid & 31) == 31) warp_sums[tid >> 5] = x;
    __syncthreads();
    if (tid < 8) {
        int y = warp_sums[tid];
        #pragma unroll
        for (int d = 1; d < 8; d <<= 1) {
            int z = __shfl_up_sync(0xffu, y, d);
            if (tid >= d) y += z;
        }
        warp_sums[tid] = y;
    }
    __syncthreads();
    int incl = x + ((tid >= 32) ? warp_sums[(tid >> 5) - 1] : 0);
    int excl = incl - v + prefix;
    if (i < NN) {
        g_offs[i] = excl;
        g_cursor[i] = excl;
        g_dinv[i] = rsqrtf((float)v + 1.0f);
    }
    if (blockIdx.x == 0 && tid == 0) g_offs[NN] = ne;
}

// ---------------- CSR scatter with fused edge weight ---------------------------
__global__ void k_scatter(const int* __restrict__ src,
                          const int* __restrict__ dst, int ne) {
    int i = blockIdx.x * blockDim.x + threadIdx.x;
    if (i < ne) {
        int d = dst[i];
        int sN = src[i];
        float w = g_dinv[d] * g_dinv[sN];
        int pos = atomicAdd(&g_cursor[d], 1);
        __stcs(&g_edge[pos], make_float2(__int_as_float(sN), w));
    }
}

// ---------------- tf32 tensor-core GEMM with fp32 + fp16 dual epilogue ---------
#define WS_STRIDE 136
#define AS_STRIDE 36
#define A_CHUNK_FLOATS (128 * AS_STRIDE)
#define GEMM_SMEM ((128 * WS_STRIDE + 2 * A_CHUNK_FLOATS) * 4)   // 106,496 B

__global__ __launch_bounds__(256, 2) void k_gemm_tf32(const float* __restrict__ A,
                                                      const float* __restrict__ W,
                                                      float* __restrict__ C,
                                                      __half* __restrict__ Ch, int nrows) {
    extern __shared__ float smem[];
    float* Ws = smem;                         // [128][136] tf32-converted
    float* As = smem + 128 * WS_STRIDE;       // [2][128][36] fp32

    int tid = threadIdx.x;
    int row0 = blockIdx.x * 128;
    uint32_t as_base = (uint32_t)__cvta_generic_to_shared(As);

    for (int i = tid; i < 128 * 32; i += 256) {
        int r = i >> 5, c = i & 31;
        float4 v = ((const float4*)(W + (size_t)r * FD))[c];
        float* d = Ws + r * WS_STRIDE + c * 4;
        d[0] = __uint_as_float(f2tf32(v.x));
        d[1] = __uint_as_float(f2tf32(v.y));
        d[2] = __uint_as_float(f2tf32(v.z));
        d[3] = __uint_as_float(f2tf32(v.w));
    }

    auto load_chunk = [&](int c, int buf) {
        #pragma unroll
        for (int i = 0; i < 4; i++) {
            int idx = tid + i * 256;
            int r = idx >> 3;
            int q = idx & 7;
            const float* g = A + (size_t)(row0 + r) * FD + c * 32 + q * 4;
            uint32_t s = as_base + (uint32_t)(buf * A_CHUNK_FLOATS + r * AS_STRIDE + q * 4) * 4;
            cp_async16(s, g, (row0 + r < nrows) ? 16 : 0);
        }
    };

    int lane = tid & 31;
    int wid  = tid >> 5;
    int wr = wid & 3;
    int wc = wid >> 2;
    int qrow = lane >> 2;
    int qcol = lane & 3;

    float acc[2][8][4];
    #pragma unroll
    for (int s = 0; s < 2; s++)
        #pragma unroll
        for (int t = 0; t < 8; t++)
            #pragma unroll
            for (int q = 0; q < 4; q++) acc[s][t][q] = 0.f;

    load_chunk(0, 0);
    asm volatile("cp.async.commit_group;" ::: "memory");

    #pragma unroll
    for (int c = 0; c < 4; c++) {
        int buf = c & 1;
        if (c < 3) {
            load_chunk(c + 1, buf ^ 1);
            asm volatile("cp.async.commit_group;" ::: "memory");
            asm volatile("cp.async.wait_group 1;" ::: "memory");
        } else {
            asm volatile("cp.async.wait_group 0;" ::: "memory");
        }
        __syncthreads();

        const float* Ab = As + buf * A_CHUNK_FLOATS;
        #pragma unroll
        for (int kk2 = 0; kk2 < 4; kk2++) {
            int k0 = kk2 * 8;
            int K0 = c * 32 + k0;
            uint32_t af[2][4];
            #pragma unroll
            for (int s = 0; s < 2; s++) {
                int rb = 32 * wr + 16 * s + qrow;
                af[s][0] = f2tf32(Ab[(rb)     * AS_STRIDE + k0 + qcol]);
                af[s][1] = f2tf32(Ab[(rb + 8) * AS_STRIDE + k0 + qcol]);
                af[s][2] = f2tf32(Ab[(rb)     * AS_STRIDE + k0 + qcol + 4]);
                af[s][3] = f2tf32(Ab[(rb + 8) * AS_STRIDE + k0 + qcol + 4]);
            }
            #pragma unroll
            for (int t = 0; t < 8; t++) {
                int n = 64 * wc + 8 * t + qrow;
                uint32_t b0 = __float_as_uint(Ws[(K0 + qcol)     * WS_STRIDE + n]);
                uint32_t b1 = __float_as_uint(Ws[(K0 + qcol + 4) * WS_STRIDE + n]);
                mma_tf32(acc[0][t], af[0], b0, b1);
                mma_tf32(acc[1][t], af[1], b0, b1);
            }
        }
        __syncthreads();
    }

    #pragma unroll
    for (int s = 0; s < 2; s++) {
        int rbase = row0 + 32 * wr + 16 * s + qrow;
        #pragma unroll
        for (int t = 0; t < 8; t++) {
            int col = 64 * wc + 8 * t + 2 * qcol;
            float2 lo = make_float2(acc[s][t][0], acc[s][t][1]);
            float2 hi = make_float2(acc[s][t][2], acc[s][t][3]);
            if (rbase < nrows) {
                *(float2*)(C + (size_t)rbase * FD + col) = lo;
                *(__half2*)(Ch + (size_t)rbase * FD + col) = __float22half2_rn(lo);
            }
            if (rbase + 8 < nrows) {
                *(float2*)(C + (size_t)(rbase + 8) * FD + col) = hi;
                *(__half2*)(Ch + (size_t)(rbase + 8) * FD + col) = __float22half2_rn(hi);
            }
        }
    }
}

// ---------------- GCN aggregation: warp/node, fp16 gathers, fp32 accum ---------
__global__ void k_agg(const float* __restrict__ h, const __half* __restrict__ hh,
                      const float* __restrict__ bias, float* __restrict__ out) {
    int gw = (blockIdx.x * blockDim.x + threadIdx.x) >> 5;
    if (gw >= NN) return;
    int lane = threadIdx.x & 31;
    int s = g_offs[gw], e = g_offs[gw + 1];

    float4 acc0 = make_float4(0.f, 0.f, 0.f, 0.f);
    float4 acc1 = make_float4(0.f, 0.f, 0.f, 0.f);

    for (int j = s; j < e; j += 8) {
        float2 ed[8];
        #pragma unroll
        for (int u = 0; u < 8; u++) {
            int jj = (j + u < e) ? j + u : e - 1;      // clamp (loop runs only if e > s)
            ed[u] = __ldcs(&g_edge[jj]);
            if (j + u >= e) ed[u].y = 0.f;             // zero weight for tail dups
        }
        uint2 q[8];
        #pragma unroll
        for (int u = 0; u < 8; u++)
            q[u] = *(const uint2*)(hh + (size_t)__float_as_int(ed[u].x) * FD + lane * 4);
        #pragma unroll
        for (int u = 0; u < 8; u += 2) {
            float2 a01 = __half22float2(*(const __half2*)&q[u].x);
            float2 a23 = __half22float2(*(const __half2*)&q[u].y);
            float2 b01 = __half22float2(*(const __half2*)&q[u + 1].x);
            float2 b23 = __half22float2(*(const __half2*)&q[u + 1].y);
            acc0.x = fmaf(ed[u].y, a01.x, acc0.x); acc0.y = fmaf(ed[u].y, a01.y, acc0.y);
            acc0.z = fmaf(ed[u].y, a23.x, acc0.z); acc0.w = fmaf(ed[u].y, a23.y, acc0.w);
            acc1.x = fmaf(ed[u+1].y, b01.x, acc1.x); acc1.y = fmaf(ed[u+1].y, b01.y, acc1.y);
            acc1.z = fmaf(ed[u+1].y, b23.x, acc1.z); acc1.w = fmaf(ed[u+1].y, b23.y, acc1.w);
        }
    }
    {   // self loop from fp32 copy (coalesced, exact)
        float di = g_dinv[gw];
        float w = di * di;
        float4 v = ((const float4*)(h + (size_t)gw * FD))[lane];
        acc0.x = fmaf(w, v.x, acc0.x); acc0.y = fmaf(w, v.y, acc0.y);
        acc0.z = fmaf(w, v.z, acc0.z); acc0.w = fmaf(w, v.w, acc0.w);
    }
    float4 b4 = ((const float4*)bias)[lane];
    float4 r;
    r.x = fmaxf(acc0.x + acc1.x + b4.x, 0.f);
    r.y = fmaxf(acc0.y + acc1.y + b4.y, 0.f);
    r.z = fmaxf(acc0.z + acc1.z + b4.z, 0.f);
    r.w = fmaxf(acc0.w + acc1.w + b4.w, 0.f);
    __stcs((float4*)(out + (size_t)gw * FD) + lane, r);
}

// ---------------- per-graph mean pool (binary-search boundaries) ---------------
__global__ void k_pool(const float* __restrict__ h, const int* __restrict__ bat) {
    int g = blockIdx.x;
    __shared__ int se[2];
    if (threadIdx.x < 2) {
        int target = g + threadIdx.x;
        int lo = 0, hi = NN;
        while (lo < hi) { int m = (lo + hi) >> 1; if (bat[m] < target) lo = m + 1; else hi = m; }
        se[threadIdx.x] = lo;
    }
    __syncthreads();
    int s = se[0], e = se[1];
    int c = blockIdx.y * 32 + threadIdx.x;   // gridDim.y = 4
    float acc0 = 0.f, acc1 = 0.f, acc2 = 0.f, acc3 = 0.f;
    int i = s;
    for (; i + 4 <= e; i += 4) {
        acc0 += h[(size_t)(i + 0) * FD + c];
        acc1 += h[(size_t)(i + 1) * FD + c];
        acc2 += h[(size_t)(i + 2) * FD + c];
        acc3 += h[(size_t)(i + 3) * FD + c];
    }
    for (; i < e; i++) acc0 += h[(size_t)i * FD + c];
    float cnt = (float)((e - s) > 1 ? (e - s) : 1);
    g_pooled[g * FD + c] = (acc0 + acc1 + acc2 + acc3) / cnt;
}

// ---------------- final FC -------------------------------------------------------
__global__ void k_fc(const float* __restrict__ fcW, const float* __restrict__ fcb,
                     float* __restrict__ out) {
    int g = blockIdx.x;
    int c = threadIdx.x;
    float acc = fcb[c];
    #pragma unroll 4
    for (int k = 0; k < FD; k++)
        acc = fmaf(g_pooled[g * FD + k], fcW[k * NC + c], acc);
    out[g * NC + c] = acc;
}

// ---------------- cleanup: restore zero state for next graph replay -------------
__global__ void k_cleanup() {
    int i = blockIdx.x * blockDim.x + threadIdx.x;
    if (i < NN) g_deg[i] = 0;
}

// ---------------- launch ----------------------------------------------------------
extern "C" void kernel_launch(void* const* d_in, const int* in_sizes, int n_in,
                              void* d_out, int out_size) {
    const float* x    = (const float*)d_in[0];
    const int*   ei   = (const int*)d_in[1];
    const int*   bat  = (const int*)d_in[2];
    const float* W1   = (const float*)d_in[3];
    const float* b1   = (const float*)d_in[4];
    const float* W2   = (const float*)d_in[5];
    const float* b2   = (const float*)d_in[6];
    const float* fcW  = (const float*)d_in[7];
    const float* fcb  = (const float*)d_in[8];
    float* out = (float*)d_out;

    int ne = in_sizes[1] / 2;
    const int* src = ei;
    const int* dst = ei + ne;

    float *bufA, *bufB;
    __half *bufAh;
    cudaGetSymbolAddress((void**)&bufA, g_bufA);
    cudaGetSymbolAddress((void**)&bufB, g_bufB);
    cudaGetSymbolAddress((void**)&bufAh, g_bufAh);

    cudaFuncSetAttribute(k_gemm_tf32, cudaFuncAttributeMaxDynamicSharedMemorySize, GEMM_SMEM);

    int tb = 256;
    int gbN   = (NN + tb - 1) / tb;
    int gbE   = (ne + tb - 1) / tb;
    int gbAgg = (NN * 32 + tb - 1) / tb;
    int gbGemm = (NN + 127) / 128;

    // launch index 3 (profiled slot) = layer-1 GEMM (validate dual epilogue)
    k_deg<<<gbE, tb>>>(dst, ne);                                        // 0
    k_blocksum<<<NBLK, tb>>>();                                         // 1
    k_offsets<<<NBLK, tb>>>(ne);                                        // 2
    k_gemm_tf32<<<gbGemm, tb, GEMM_SMEM>>>(x, W1, bufA, bufAh, NN);     // 3 <- profiled
    k_scatter<<<gbE, tb>>>(src, dst, ne);                               // 4
    k_agg<<<gbAgg, tb>>>(bufA, bufAh, b1, bufB);                        // 5
    k_gemm_tf32<<<gbGemm, tb, GEMM_SMEM>>>(bufB, W2, bufA, bufAh, NN);  // 6
    k_agg<<<gbAgg, tb>>>(bufA, bufAh, b2, bufB);                        // 7
    k_pool<<<dim3(NG, 4), 32>>>(bufB, bat);                             // 8
    k_fc<<<NG, NC>>>(fcW, fcb, out);                                    // 9
    k_cleanup<<<gbN, tb>>>();                                           // 10
}

// round 11
// speedup vs baseline: 1.3829x; 1.3617x over previous
#include <cuda_runtime.h>
#include <cuda_fp16.h>
#include <cstdint>

#define NN 100000
#define NE 1600000
#define FD 128
#define NG 64
#define NC 32

#define NBLK ((NN + 255) / 256)   // 391 scan blocks

// ---------------- scratch (static device globals; allocation-free) ----------
// g_deg is zero on first use and re-zeroed by k_cleanup every launch (replay-safe).
__device__ int    g_deg[NN];
__device__ int    g_offs[NN + 1];
__device__ int    g_cursor[NN];
__device__ float2 g_edge[NE];          // (.x = src idx bitcast, .y = weight)
__device__ float  g_dinv[NN];
__device__ int    g_bsum[NBLK];
__device__ float  g_bufA[(size_t)NN * FD];    // gemm out fp32
__device__ __half g_bufAh[(size_t)NN * FD];   // gemm out fp16 (gather mirror)
__device__ float  g_bufB[(size_t)NN * FD];    // agg out fp32
__device__ float  g_pooled[NG * FD];

// ---------------- helpers -----------------------------------------------------
__device__ __forceinline__ uint32_t f2tf32(float x) {
    uint32_t r; asm("cvt.rna.tf32.f32 %0, %1;" : "=r"(r) : "f"(x)); return r;
}

__device__ __forceinline__ void mma_tf32(float* d, const uint32_t* a, uint32_t b0, uint32_t b1) {
    asm volatile("mma.sync.aligned.m16n8k8.row.col.f32.tf32.tf32.f32 "
                 "{%0,%1,%2,%3}, {%4,%5,%6,%7}, {%8,%9}, {%0,%1,%2,%3};"
                 : "+f"(d[0]), "+f"(d[1]), "+f"(d[2]), "+f"(d[3])
                 : "r"(a[0]), "r"(a[1]), "r"(a[2]), "r"(a[3]), "r"(b0), "r"(b1));
}

__device__ __forceinline__ void cp_async16(uint32_t saddr, const void* gptr, int src_bytes) {
    asm volatile("cp.async.ca.shared.global [%0], [%1], 16, %2;"
                 :: "r"(saddr), "l"(gptr), "r"(src_bytes));
}

// ---------------- degree histogram ----------------------------------------------
__global__ void k_deg(const int* __restrict__ dst, int ne) {
    int i = blockIdx.x * blockDim.x + threadIdx.x;
    if (i < ne) atomicAdd(&g_deg[dst[i]], 1);
}

// ---------------- block sums ------------------------------------------------------
__global__ void k_blocksum() {
    __shared__ int s[256];
    int i = blockIdx.x * 256 + threadIdx.x;
    s[threadIdx.x] = (i < NN) ? g_deg[i] : 0;
    __syncthreads();
    for (int d = 128; d > 0; d >>= 1) {
        if (threadIdx.x < d) s[threadIdx.x] += s[threadIdx.x + d];
        __syncthreads();
    }
    if (threadIdx.x == 0) g_bsum[blockIdx.x] = s[0];
}

// ---------------- offsets: fused block-prefix + intra-block scan + dinv ----------
__global__ void k_offsets(int ne) {
    __shared__ int red[8];
    __shared__ int warp_sums[8];
    __shared__ int s_prefix;
    int tid = threadIdx.x;

    int p = 0;
    for (int i = tid; i < blockIdx.x; i += 256) p += g_bsum[i];
    #pragma unroll
    for (int d = 16; d; d >>= 1) p += __shfl_down_sync(0xffffffffu, p, d);
    if ((tid & 31) == 0) red[tid >> 5] = p;
    __syncthreads();
    if (tid == 0) {
        int t = 0;
        #pragma unroll
        for (int w = 0; w < 8; w++) t += red[w];
        s_prefix = t;
    }
    __syncthreads();
    int prefix = s_prefix;

    int i = blockIdx.x * 256 + tid;
    int v = (i < NN) ? g_deg[i] : 0;
    int x = v;
    #pragma unroll
    for (int d = 1; d < 32; d <<= 1) {
        int y = __shfl_up_sync(0xffffffffu, x, d);
        if ((tid & 31) >= d) x += y;
    }
    if ((tid & 31) == 31) warp_sums[tid >> 5] = x;
    __syncthreads();
    if (tid < 8) {
        int y = warp_sums[tid];
        #pragma unroll
        for (int d = 1; d < 8; d <<= 1) {
            int z = __shfl_up_sync(0xffu, y, d);
            if (tid >= d) y += z;
        }
        warp_sums[tid] = y;
    }
    __syncthreads();
    int incl = x + ((tid >= 32) ? warp_sums[(tid >> 5) - 1] : 0);
    int excl = incl - v + prefix;
    if (i < NN) {
        g_offs[i] = excl;
        g_cursor[i] = excl;
        g_dinv[i] = rsqrtf((float)v + 1.0f);
    }
    if (blockIdx.x == 0 && tid == 0) g_offs[NN] = ne;
}

// ---------------- CSR scatter with fused edge weight ---------------------------
__global__ void k_scatter(const int* __restrict__ src,
                          const int* __restrict__ dst, int ne) {
    int i = blockIdx.x * blockDim.x + threadIdx.x;
    if (i < ne) {
        int d = dst[i];
        int sN = src[i];
        float w = g_dinv[d] * g_dinv[sN];
        int pos = atomicAdd(&g_cursor[d], 1);
        __stcs(&g_edge[pos], make_float2(__int_as_float(sN), w));
    }
}

// ---------------- tf32 tensor-core GEMM with fp32 + fp16 dual epilogue ---------
#define WS_STRIDE 136
#define AS_STRIDE 36
#define A_CHUNK_FLOATS (128 * AS_STRIDE)
#define GEMM_SMEM ((128 * WS_STRIDE + 2 * A_CHUNK_FLOATS) * 4)   // 106,496 B

__global__ __launch_bounds__(256, 2) void k_gemm_tf32(const float* __restrict__ A,
                                                      const float* __restrict__ W,
                                                      float* __restrict__ C,
                                                      __half* __restrict__ Ch, int nrows) {
    extern __shared__ float smem[];
    float* Ws = smem;                         // [128][136] tf32-converted
    float* As = smem + 128 * WS_STRIDE;       // [2][128][36] fp32

    int tid = threadIdx.x;
    int row0 = blockIdx.x * 128;
    uint32_t as_base = (uint32_t)__cvta_generic_to_shared(As);

    for (int i = tid; i < 128 * 32; i += 256) {
        int r = i >> 5, c = i & 31;
        float4 v = ((const float4*)(W + (size_t)r * FD))[c];
        float* d = Ws + r * WS_STRIDE + c * 4;
        d[0] = __uint_as_float(f2tf32(v.x));
        d[1] = __uint_as_float(f2tf32(v.y));
        d[2] = __uint_as_float(f2tf32(v.z));
        d[3] = __uint_as_float(f2tf32(v.w));
    }

    auto load_chunk = [&](int c, int buf) {
        #pragma unroll
        for (int i = 0; i < 4; i++) {
            int idx = tid + i * 256;
            int r = idx >> 3;
            int q = idx & 7;
            const float* g = A + (size_t)(row0 + r) * FD + c * 32 + q * 4;
            uint32_t s = as_base + (uint32_t)(buf * A_CHUNK_FLOATS + r * AS_STRIDE + q * 4) * 4;
            cp_async16(s, g, (row0 + r < nrows) ? 16 : 0);
        }
    };

    int lane = tid & 31;
    int wid  = tid >> 5;
    int wr = wid & 3;
    int wc = wid >> 2;
    int qrow = lane >> 2;
    int qcol = lane & 3;

    float acc[2][8][4];
    #pragma unroll
    for (int s = 0; s < 2; s++)
        #pragma unroll
        for (int t = 0; t < 8; t++)
            #pragma unroll
            for (int q = 0; q < 4; q++) acc[s][t][q] = 0.f;

    load_chunk(0, 0);
    asm volatile("cp.async.commit_group;" ::: "memory");

    #pragma unroll
    for (int c = 0; c < 4; c++) {
        int buf = c & 1;
        if (c < 3) {
            load_chunk(c + 1, buf ^ 1);
            asm volatile("cp.async.commit_group;" ::: "memory");
            asm volatile("cp.async.wait_group 1;" ::: "memory");
        } else {
            asm volatile("cp.async.wait_group 0;" ::: "memory");
        }
        __syncthreads();

        const float* Ab = As + buf * A_CHUNK_FLOATS;
        #pragma unroll
        for (int kk2 = 0; kk2 < 4; kk2++) {
            int k0 = kk2 * 8;
            int K0 = c * 32 + k0;
            uint32_t af[2][4];
            #pragma unroll
            for (int s = 0; s < 2; s++) {
                int rb = 32 * wr + 16 * s + qrow;
                af[s][0] = f2tf32(Ab[(rb)     * AS_STRIDE + k0 + qcol]);
                af[s][1] = f2tf32(Ab[(rb + 8) * AS_STRIDE + k0 + qcol]);
                af[s][2] = f2tf32(Ab[(rb)     * AS_STRIDE + k0 + qcol + 4]);
                af[s][3] = f2tf32(Ab[(rb + 8) * AS_STRIDE + k0 + qcol + 4]);
            }
            #pragma unroll
            for (int t = 0; t < 8; t++) {
                int n = 64 * wc + 8 * t + qrow;
                uint32_t b0 = __float_as_uint(Ws[(K0 + qcol)     * WS_STRIDE + n]);
                uint32_t b1 = __float_as_uint(Ws[(K0 + qcol + 4) * WS_STRIDE + n]);
                mma_tf32(acc[0][t], af[0], b0, b1);
                mma_tf32(acc[1][t], af[1], b0, b1);
            }
        }
        __syncthreads();
    }

    #pragma unroll
    for (int s = 0; s < 2; s++) {
        int rbase = row0 + 32 * wr + 16 * s + qrow;
        #pragma unroll
        for (int t = 0; t < 8; t++) {
            int col = 64 * wc + 8 * t + 2 * qcol;
            float2 lo = make_float2(acc[s][t][0], acc[s][t][1]);
            float2 hi = make_float2(acc[s][t][2], acc[s][t][3]);
            if (rbase < nrows) {
                *(float2*)(C + (size_t)rbase * FD + col) = lo;
                *(__half2*)(Ch + (size_t)rbase * FD + col) = __float22half2_rn(lo);
            }
            if (rbase + 8 < nrows) {
                *(float2*)(C + (size_t)(rbase + 8) * FD + col) = hi;
                *(__half2*)(Ch + (size_t)(rbase + 8) * FD + col) = __float22half2_rn(hi);
            }
        }
    }
}

// ---------------- GCN aggregation: 2 warps/node (feature split), fp16 gathers ---
__global__ void k_agg(const float* __restrict__ h, const __half* __restrict__ hh,
                      const float* __restrict__ bias, float* __restrict__ out) {
    int gwarp = (blockIdx.x * blockDim.x + threadIdx.x) >> 5;
    int node = gwarp >> 1;
    if (node >= NN) return;
    int half = gwarp & 1;
    int lane = threadIdx.x & 31;
    int coff = half * 64 + lane * 2;          // 2 fp16 cols per lane
    int s = g_offs[node], e = g_offs[node + 1];

    const __half* hb = hh + coff;

    float2 acc0 = make_float2(0.f, 0.f);
    float2 acc1 = make_float2(0.f, 0.f);

    for (int j = s; j < e; j += 8) {
        float2 ed[8];
        #pragma unroll
        for (int u = 0; u < 8; u++) {
            int jj = (j + u < e) ? j + u : e - 1;      // clamp (loop runs only if e > s)
            ed[u] = __ldcs(&g_edge[jj]);
            if (j + u >= e) ed[u].y = 0.f;             // zero weight for tail dups
        }
        uint32_t q[8];
        #pragma unroll
        for (int u = 0; u < 8; u++)
            q[u] = *(const uint32_t*)(hb + (size_t)__float_as_int(ed[u].x) * FD);
        #pragma unroll
        for (int u = 0; u < 8; u += 2) {
            float2 a = __half22float2(*(const __half2*)&q[u]);
            float2 b = __half22float2(*(const __half2*)&q[u + 1]);
            acc0.x = fmaf(ed[u].y, a.x, acc0.x);
            acc0.y = fmaf(ed[u].y, a.y, acc0.y);
            acc1.x = fmaf(ed[u + 1].y, b.x, acc1.x);
            acc1.y = fmaf(ed[u + 1].y, b.y, acc1.y);
        }
    }
    {   // self loop from fp32 copy (exact)
        float di = g_dinv[node];
        float w = di * di;
        float2 v = *(const float2*)(h + (size_t)node * FD + coff);
        acc0.x = fmaf(w, v.x, acc0.x);
        acc0.y = fmaf(w, v.y, acc0.y);
    }
    float2 bv = *(const float2*)(bias + coff);
    float2 r;
    r.x = fmaxf(acc0.x + acc1.x + bv.x, 0.f);
    r.y = fmaxf(acc0.y + acc1.y + bv.y, 0.f);
    __stcs((float2*)(out + (size_t)node * FD + coff), r);
}

// ---------------- per-graph mean pool: 1024 thr/graph, 8 row-stripes ------------
__global__ void k_pool(const float* __restrict__ h, const int* __restrict__ bat) {
    int g = blockIdx.x;
    __shared__ int se[2];
    __shared__ float part[7][FD];
    if (threadIdx.x < 2) {
        int target = g + threadIdx.x;
        int lo = 0, hi = NN;
        while (lo < hi) { int m = (lo + hi) >> 1; if (bat[m] < target) lo = m + 1; else hi = m; }
        se[threadIdx.x] = lo;
    }
    __syncthreads();
    int s = se[0], e = se[1];
    int c = threadIdx.x & 127;
    int r0 = threadIdx.x >> 7;    // 0..7
    float acc = 0.f;
    for (int i = s + r0; i < e; i += 8)
        acc += h[(size_t)i * FD + c];
    if (r0 > 0) part[r0 - 1][c] = acc;
    __syncthreads();
    if (r0 == 0) {
        #pragma unroll
        for (int u = 0; u < 7; u++) acc += part[u][c];
        float cnt = (float)((e - s) > 1 ? (e - s) : 1);
        g_pooled[g * FD + c] = acc / cnt;
    }
}

// ---------------- final FC -------------------------------------------------------
__global__ void k_fc(const float* __restrict__ fcW, const float* __restrict__ fcb,
                     float* __restrict__ out) {
    int g = blockIdx.x;
    int c = threadIdx.x;
    float acc = fcb[c];
    #pragma unroll 4
    for (int k = 0; k < FD; k++)
        acc = fmaf(g_pooled[g * FD + k], fcW[k * NC + c], acc);
    out[g * NC + c] = acc;
}

// ---------------- cleanup: restore zero state for next graph replay -------------
__global__ void k_cleanup() {
    int i = blockIdx.x * blockDim.x + threadIdx.x;
    if (i < NN) g_deg[i] = 0;
}

// ---------------- launch ----------------------------------------------------------
extern "C" void kernel_launch(void* const* d_in, const int* in_sizes, int n_in,
                              void* d_out, int out_size) {
    const float* x    = (const float*)d_in[0];
    const int*   ei   = (const int*)d_in[1];
    const int*   bat  = (const int*)d_in[2];
    const float* W1   = (const float*)d_in[3];
    const float* b1   = (const float*)d_in[4];
    const float* W2   = (const float*)d_in[5];
    const float* b2   = (const float*)d_in[6];
    const float* fcW  = (const float*)d_in[7];
    const float* fcb  = (const float*)d_in[8];
    float* out = (float*)d_out;

    int ne = in_sizes[1] / 2;
    const int* src = ei;
    const int* dst = ei + ne;

    float *bufA, *bufB;
    __half *bufAh;
    cudaGetSymbolAddress((void**)&bufA, g_bufA);
    cudaGetSymbolAddress((void**)&bufB, g_bufB);
    cudaGetSymbolAddress((void**)&bufAh, g_bufAh);

    cudaFuncSetAttribute(k_gemm_tf32, cudaFuncAttributeMaxDynamicSharedMemorySize, GEMM_SMEM);

    int tb = 256;
    int gbN   = (NN + tb - 1) / tb;
    int gbE   = (ne + tb - 1) / tb;
    int gbAgg = (NN * 2 * 32 + tb - 1) / tb;    // 2 warps per node
    int gbGemm = (NN + 127) / 128;

    k_deg<<<gbE, tb>>>(dst, ne);                                        // 0
    k_blocksum<<<NBLK, tb>>>();                                         // 1
    k_offsets<<<NBLK, tb>>>(ne);                                        // 2
    k_gemm_tf32<<<gbGemm, tb, GEMM_SMEM>>>(x, W1, bufA, bufAh, NN);     // 3 <- profiled
    k_scatter<<<gbE, tb>>>(src, dst, ne);                               // 4
    k_agg<<<gbAgg, tb>>>(bufA, bufAh, b1, bufB);                        // 5
    k_gemm_tf32<<<gbGemm, tb, GEMM_SMEM>>>(bufB, W2, bufA, bufAh, NN);  // 6
    k_agg<<<gbAgg, tb>>>(bufA, bufAh, b2, bufB);                        // 7
    k_pool<<<NG, 1024>>>(bufB, bat);                                    // 8
    k_fc<<<NG, NC>>>(fcW, fcb, out);                                    // 9
    k_cleanup<<<gbN, tb>>>();                                           // 10
}

// round 12
// speedup vs baseline: 1.3870x; 1.0030x over previous
#include <cuda_runtime.h>
#include <cuda_fp16.h>
#include <cstdint>

#define NN 100000
#define NE 1600000
#define FD 128
#define NG 64
#define NC 32

#define NBLK ((NN + 255) / 256)   // 391 scan blocks

// ---------------- scratch (static device globals; allocation-free) ----------
// g_deg is zero on first use and re-zeroed by k_cleanup every launch (replay-safe).
__device__ int    g_deg[NN];
__device__ int    g_offs[NN + 1];
__device__ int    g_cursor[NN];
__device__ float2 g_edge[NE];          // (.x = src idx bitcast, .y = weight)
__device__ float  g_dinv[NN];
__device__ int    g_bsum[NBLK];
__device__ __half g_bufAh[(size_t)NN * FD];   // gemm out fp16 (gather source)
__device__ float  g_bufB[(size_t)NN * FD];    // agg out fp32
__device__ float  g_pooled[NG * FD];

// ---------------- helpers -----------------------------------------------------
__device__ __forceinline__ uint32_t f2tf32(float x) {
    uint32_t r; asm("cvt.rna.tf32.f32 %0, %1;" : "=r"(r) : "f"(x)); return r;
}

__device__ __forceinline__ void mma_tf32(float* d, const uint32_t* a, uint32_t b0, uint32_t b1) {
    asm volatile("mma.sync.aligned.m16n8k8.row.col.f32.tf32.tf32.f32 "
                 "{%0,%1,%2,%3}, {%4,%5,%6,%7}, {%8,%9}, {%0,%1,%2,%3};"
                 : "+f"(d[0]), "+f"(d[1]), "+f"(d[2]), "+f"(d[3])
                 : "r"(a[0]), "r"(a[1]), "r"(a[2]), "r"(a[3]), "r"(b0), "r"(b1));
}

__device__ __forceinline__ void cp_async16(uint32_t saddr, const void* gptr, int src_bytes) {
    asm volatile("cp.async.ca.shared.global [%0], [%1], 16, %2;"
                 :: "r"(saddr), "l"(gptr), "r"(src_bytes));
}

// ---------------- degree histogram ----------------------------------------------
__global__ void k_deg(const int* __restrict__ dst, int ne) {
    int i = blockIdx.x * blockDim.x + threadIdx.x;
    if (i < ne) atomicAdd(&g_deg[dst[i]], 1);
}

// ---------------- block sums ------------------------------------------------------
__global__ void k_blocksum() {
    __shared__ int s[256];
    int i = blockIdx.x * 256 + threadIdx.x;
    s[threadIdx.x] = (i < NN) ? g_deg[i] : 0;
    __syncthreads();
    for (int d = 128; d > 0; d >>= 1) {
        if (threadIdx.x < d) s[threadIdx.x] += s[threadIdx.x + d];
        __syncthreads();
    }
    if (threadIdx.x == 0) g_bsum[blockIdx.x] = s[0];
}

// ---------------- offsets: fused block-prefix + intra-block scan + dinv ----------
__global__ void k_offsets(int ne) {
    __shared__ int red[8];
    __shared__ int warp_sums[8];
    __shared__ int s_prefix;
    int tid = threadIdx.x;

    int p = 0;
    for (int i = tid; i < blockIdx.x; i += 256) p += g_bsum[i];
    #pragma unroll
    for (int d = 16; d; d >>= 1) p += __shfl_down_sync(0xffffffffu, p, d);
    if ((tid & 31) == 0) red[tid >> 5] = p;
    __syncthreads();
    if (tid == 0) {
        int t = 0;
        #pragma unroll
        for (int w = 0; w < 8; w++) t += red[w];
        s_prefix = t;
    }
    __syncthreads();
    int prefix = s_prefix;

    int i = blockIdx.x * 256 + tid;
    int v = (i < NN) ? g_deg[i] : 0;
    int x = v;
    #pragma unroll
    for (int d = 1; d < 32; d <<= 1) {
        int y = __shfl_up_sync(0xffffffffu, x, d);
        if ((tid & 31) >= d) x += y;
    }
    if ((tid & 31) == 31) warp_sums[tid >> 5] = x;
    __syncthreads();
    if (tid < 8) {
        int y = warp_sums[tid];
        #pragma unroll
        for (int d = 1; d < 8; d <<= 1) {
            int z = __shfl_up_sync(0xffu, y, d);
            if (tid >= d) y += z;
        }
        warp_sums[tid] = y;
    }
    __syncthreads();
    int incl = x + ((tid >= 32) ? warp_sums[(tid >> 5) - 1] : 0);
    int excl = incl - v + prefix;
    if (i < NN) {
        g_offs[i] = excl;
        g_cursor[i] = excl;
        g_dinv[i] = rsqrtf((float)v + 1.0f);
    }
    if (blockIdx.x == 0 && tid == 0) g_offs[NN] = ne;
}

// ---------------- CSR scatter with fused edge weight ---------------------------
__global__ void k_scatter(const int* __restrict__ src,
                          const int* __restrict__ dst, int ne) {
    int i = blockIdx.x * blockDim.x + threadIdx.x;
    if (i < ne) {
        int d = dst[i];
        int sN = src[i];
        float w = g_dinv[d] * g_dinv[sN];
        int pos = atomicAdd(&g_cursor[d], 1);
        __stcs(&g_edge[pos], make_float2(__int_as_float(sN), w));
    }
}

// ---------------- tf32 tensor-core GEMM, fp16-only epilogue --------------------
#define WS_STRIDE 136
#define AS_STRIDE 36
#define A_CHUNK_FLOATS (128 * AS_STRIDE)
#define GEMM_SMEM ((128 * WS_STRIDE + 2 * A_CHUNK_FLOATS) * 4)   // 106,496 B

__global__ __launch_bounds__(256, 2) void k_gemm_tf32(const float* __restrict__ A,
                                                      const float* __restrict__ W,
                                                      __half* __restrict__ Ch, int nrows) {
    extern __shared__ float smem[];
    float* Ws = smem;                         // [128][136] tf32-converted
    float* As = smem + 128 * WS_STRIDE;       // [2][128][36] fp32

    int tid = threadIdx.x;
    int row0 = blockIdx.x * 128;
    uint32_t as_base = (uint32_t)__cvta_generic_to_shared(As);

    for (int i = tid; i < 128 * 32; i += 256) {
        int r = i >> 5, c = i & 31;
        float4 v = ((const float4*)(W + (size_t)r * FD))[c];
        float* d = Ws + r * WS_STRIDE + c * 4;
        d[0] = __uint_as_float(f2tf32(v.x));
        d[1] = __uint_as_float(f2tf32(v.y));
        d[2] = __uint_as_float(f2tf32(v.z));
        d[3] = __uint_as_float(f2tf32(v.w));
    }

    auto load_chunk = [&](int c, int buf) {
        #pragma unroll
        for (int i = 0; i < 4; i++) {
            int idx = tid + i * 256;
            int r = idx >> 3;
            int q = idx & 7;
            const float* g = A + (size_t)(row0 + r) * FD + c * 32 + q * 4;
            uint32_t s = as_base + (uint32_t)(buf * A_CHUNK_FLOATS + r * AS_STRIDE + q * 4) * 4;
            cp_async16(s, g, (row0 + r < nrows) ? 16 : 0);
        }
    };

    int lane = tid & 31;
    int wid  = tid >> 5;
    int wr = wid & 3;
    int wc = wid >> 2;
    int qrow = lane >> 2;
    int qcol = lane & 3;

    float acc[2][8][4];
    #pragma unroll
    for (int s = 0; s < 2; s++)
        #pragma unroll
        for (int t = 0; t < 8; t++)
            #pragma unroll
            for (int q = 0; q < 4; q++) acc[s][t][q] = 0.f;

    load_chunk(0, 0);
    asm volatile("cp.async.commit_group;" ::: "memory");

    #pragma unroll
    for (int c = 0; c < 4; c++) {
        int buf = c & 1;
        if (c < 3) {
            load_chunk(c + 1, buf ^ 1);
            asm volatile("cp.async.commit_group;" ::: "memory");
            asm volatile("cp.async.wait_group 1;" ::: "memory");
        } else {
            asm volatile("cp.async.wait_group 0;" ::: "memory");
        }
        __syncthreads();

        const float* Ab = As + buf * A_CHUNK_FLOATS;
        #pragma unroll
        for (int kk2 = 0; kk2 < 4; kk2++) {
            int k0 = kk2 * 8;
            int K0 = c * 32 + k0;
            uint32_t af[2][4];
            #pragma unroll
            for (int s = 0; s < 2; s++) {
                int rb = 32 * wr + 16 * s + qrow;
                af[s][0] = f2tf32(Ab[(rb)     * AS_STRIDE + k0 + qcol]);
                af[s][1] = f2tf32(Ab[(rb + 8) * AS_STRIDE + k0 + qcol]);
                af[s][2] = f2tf32(Ab[(rb)     * AS_STRIDE + k0 + qcol + 4]);
                af[s][3] = f2tf32(Ab[(rb + 8) * AS_STRIDE + k0 + qcol + 4]);
            }
            #pragma unroll
            for (int t = 0; t < 8; t++) {
                int n = 64 * wc + 8 * t + qrow;
                uint32_t b0 = __float_as_uint(Ws[(K0 + qcol)     * WS_STRIDE + n]);
                uint32_t b1 = __float_as_uint(Ws[(K0 + qcol + 4) * WS_STRIDE + n]);
                mma_tf32(acc[0][t], af[0], b0, b1);
                mma_tf32(acc[1][t], af[1], b0, b1);
            }
        }
        __syncthreads();
    }

    #pragma unroll
    for (int s = 0; s < 2; s++) {
        int rbase = row0 + 32 * wr + 16 * s + qrow;
        #pragma unroll
        for (int t = 0; t < 8; t++) {
            int col = 64 * wc + 8 * t + 2 * qcol;
            if (rbase < nrows)
                *(__half2*)(Ch + (size_t)rbase * FD + col) =
                    __float22half2_rn(make_float2(acc[s][t][0], acc[s][t][1]));
            if (rbase + 8 < nrows)
                *(__half2*)(Ch + (size_t)(rbase + 8) * FD + col) =
                    __float22half2_rn(make_float2(acc[s][t][2], acc[s][t][3]));
        }
    }
}

// ---------------- GCN aggregation: 2 warps/node, 16-wide fp16 gathers ----------
__global__ void k_agg(const __half* __restrict__ hh,
                      const float* __restrict__ bias, float* __restrict__ out) {
    int gwarp = (blockIdx.x * blockDim.x + threadIdx.x) >> 5;
    int node = gwarp >> 1;
    if (node >= NN) return;
    int half = gwarp & 1;
    int lane = threadIdx.x & 31;
    int coff = half * 64 + lane * 2;          // 2 fp16 cols per lane
    int s = g_offs[node], e = g_offs[node + 1];

    const __half* hb = hh + coff;

    float2 acc0 = make_float2(0.f, 0.f);
    float2 acc1 = make_float2(0.f, 0.f);

    for (int j = s; j < e; j += 16) {
        float2 ed[16];
        #pragma unroll
        for (int u = 0; u < 16; u++) {
            int jj = (j + u < e) ? j + u : e - 1;      // clamp (loop runs only if e > s)
            ed[u] = __ldcs(&g_edge[jj]);
            if (j + u >= e) ed[u].y = 0.f;             // zero weight for tail dups
        }
        uint32_t q[16];
        #pragma unroll
        for (int u = 0; u < 16; u++)
            q[u] = *(const uint32_t*)(hb + (size_t)__float_as_int(ed[u].x) * FD);
        #pragma unroll
        for (int u = 0; u < 16; u += 2) {
            float2 a = __half22float2(*(const __half2*)&q[u]);
            float2 b = __half22float2(*(const __half2*)&q[u + 1]);
            acc0.x = fmaf(ed[u].y, a.x, acc0.x);
            acc0.y = fmaf(ed[u].y, a.y, acc0.y);
            acc1.x = fmaf(ed[u + 1].y, b.x, acc1.x);
            acc1.y = fmaf(ed[u + 1].y, b.y, acc1.y);
        }
    }
    {   // self loop (fp16 mirror)
        float di = g_dinv[node];
        float w = di * di;
        float2 v = __half22float2(*(const __half2*)(hb + (size_t)node * FD));
        acc0.x = fmaf(w, v.x, acc0.x);
        acc0.y = fmaf(w, v.y, acc0.y);
    }
    float2 bv = *(const float2*)(bias + coff);
    float2 r;
    r.x = fmaxf(acc0.x + acc1.x + bv.x, 0.f);
    r.y = fmaxf(acc0.y + acc1.y + bv.y, 0.f);
    __stcs((float2*)(out + (size_t)node * FD + coff), r);
}

// ---------------- per-graph mean pool: 1024 thr/graph, 8 row-stripes ------------
__global__ void k_pool(const float* __restrict__ h, const int* __restrict__ bat) {
    int g = blockIdx.x;
    __shared__ int se[2];
    __shared__ float part[7][FD];
    if (threadIdx.x < 2) {
        int target = g + threadIdx.x;
        int lo = 0, hi = NN;
        while (lo < hi) { int m = (lo + hi) >> 1; if (bat[m] < target) lo = m + 1; else hi = m; }
        se[threadIdx.x] = lo;
    }
    __syncthreads();
    int s = se[0], e = se[1];
    int c = threadIdx.x & 127;
    int r0 = threadIdx.x >> 7;    // 0..7
    float acc = 0.f;
    for (int i = s + r0; i < e; i += 8)
        acc += h[(size_t)i * FD + c];
    if (r0 > 0) part[r0 - 1][c] = acc;
    __syncthreads();
    if (r0 == 0) {
        #pragma unroll
        for (int u = 0; u < 7; u++) acc += part[u][c];
        float cnt = (float)((e - s) > 1 ? (e - s) : 1);
        g_pooled[g * FD + c] = acc / cnt;
    }
}

// ---------------- final FC -------------------------------------------------------
__global__ void k_fc(const float* __restrict__ fcW, const float* __restrict__ fcb,
                     float* __restrict__ out) {
    int g = blockIdx.x;
    int c = threadIdx.x;
    float acc = fcb[c];
    #pragma unroll 4
    for (int k = 0; k < FD; k++)
        acc = fmaf(g_pooled[g * FD + k], fcW[k * NC + c], acc);
    out[g * NC + c] = acc;
}

// ---------------- cleanup: restore zero state for next graph replay -------------
__global__ void k_cleanup() {
    int i = blockIdx.x * blockDim.x + threadIdx.x;
    if (i < NN) g_deg[i] = 0;
}

// ---------------- launch ----------------------------------------------------------
extern "C" void kernel_launch(void* const* d_in, const int* in_sizes, int n_in,
                              void* d_out, int out_size) {
    const float* x    = (const float*)d_in[0];
    const int*   ei   = (const int*)d_in[1];
    const int*   bat  = (const int*)d_in[2];
    const float* W1   = (const float*)d_in[3];
    const float* b1   = (const float*)d_in[4];
    const float* W2   = (const float*)d_in[5];
    const float* b2   = (const float*)d_in[6];
    const float* fcW  = (const float*)d_in[7];
    const float* fcb  = (const float*)d_in[8];
    float* out = (float*)d_out;

    int ne = in_sizes[1] / 2;
    const int* src = ei;
    const int* dst = ei + ne;

    float *bufB;
    __half *bufAh;
    cudaGetSymbolAddress((void**)&bufB, g_bufB);
    cudaGetSymbolAddress((void**)&bufAh, g_bufAh);

    cudaFuncSetAttribute(k_gemm_tf32, cudaFuncAttributeMaxDynamicSharedMemorySize, GEMM_SMEM);

    int tb = 256;
    int gbN   = (NN + tb - 1) / tb;
    int gbE   = (ne + tb - 1) / tb;
    int gbAgg = (NN * 2 * 32 + tb - 1) / tb;    // 2 warps per node
    int gbGemm = (NN + 127) / 128;

    k_deg<<<gbE, tb>>>(dst, ne);                                        // 0
    k_blocksum<<<NBLK, tb>>>();                                         // 1
    k_offsets<<<NBLK, tb>>>(ne);                                        // 2
    k_gemm_tf32<<<gbGemm, tb, GEMM_SMEM>>>(x, W1, bufAh, NN);           // 3 <- profiled
    k_scatter<<<gbE, tb>>>(src, dst, ne);                               // 4
    k_agg<<<gbAgg, tb>>>(bufAh, b1, bufB);                              // 5
    k_gemm_tf32<<<gbGemm, tb, GEMM_SMEM>>>(bufB, W2, bufAh, NN);        // 6
    k_agg<<<gbAgg, tb>>>(bufAh, b2, bufB);                              // 7
    k_pool<<<NG, 1024>>>(bufB, bat);                                    // 8
    k_fc<<<NG, NC>>>(fcW, fcb, out);                                    // 9
    k_cleanup<<<gbN, tb>>>();                                           // 10
}

// round 13
// speedup vs baseline: 1.4352x; 1.0348x over previous
#include <cuda_runtime.h>
#include <cuda_fp16.h>
#include <cstdint>

#define NN 100000
#define NE 1600000
#define FD 128
#define NG 64
#define NC 32

#define NBLK ((NN + 255) / 256)   // 391 scan blocks

// ---------------- scratch (static device globals; allocation-free) ----------
// g_deg zero at start (static init; re-zeroed by k_cleanup). g_scanv re-zeroed
// by k_deg_x2h before every k_scan (same-stream ordering), replay-safe.
__device__ int    g_deg[NN];
__device__ int    g_offs[NN + 1];
__device__ int    g_cursor[NN];
__device__ float2 g_edge[NE];
__device__ float  g_dinv[NN];
__device__ int    g_scanv[NBLK];
__device__ __half g_xh[(size_t)NN * FD];      // fp16 X
__device__ __half g_aggh[(size_t)NN * FD];    // agg1 out / gemm2 out (reused)
__device__ __half g_h1h[(size_t)NN * FD];     // gemm1 out (relu'd h1)
__device__ float  g_bufB[(size_t)NN * FD];    // agg2 out fp32
__device__ float  g_pooled[NG * FD];

// ---------------- helpers -----------------------------------------------------
__device__ __forceinline__ void mma_f16(float* d, const uint32_t* a, uint32_t b0, uint32_t b1) {
    asm volatile("mma.sync.aligned.m16n8k16.row.col.f32.f16.f16.f32 "
                 "{%0,%1,%2,%3}, {%4,%5,%6,%7}, {%8,%9}, {%0,%1,%2,%3};"
                 : "+f"(d[0]), "+f"(d[1]), "+f"(d[2]), "+f"(d[3])
                 : "r"(a[0]), "r"(a[1]), "r"(a[2]), "r"(a[3]), "r"(b0), "r"(b1));
}

__device__ __forceinline__ void cp_async16(uint32_t saddr, const void* gptr, int src_bytes) {
    asm volatile("cp.async.ca.shared.global [%0], [%1], 16, %2;"
                 :: "r"(saddr), "l"(gptr), "r"(src_bytes));
}

// ---------------- deg histogram + x->fp16 + scan-flag reset --------------------
__global__ void k_deg_x2h(const int* __restrict__ dst, int ne,
                          const float* __restrict__ x) {
    int gid = blockIdx.x * blockDim.x + threadIdx.x;
    int stride = gridDim.x * blockDim.x;
    if (gid < ne) atomicAdd(&g_deg[dst[gid]], 1);
    if (gid < NBLK) g_scanv[gid] = 0;
    for (int i = gid; i < NN * FD / 2; i += stride) {
        float2 v = ((const float2*)x)[i];
        ((__half2*)g_xh)[i] = __float22half2_rn(v);
    }
}

// ---------------- single-kernel scan (publish totals, spin-read predecessors) --
__global__ void k_scan(int ne) {
    __shared__ int warp_sums[8];
    __shared__ int red[8];
    __shared__ int s_prefix;
    int tid = threadIdx.x, bid = blockIdx.x;
    int i = bid * 256 + tid;
    int v = (i < NN) ? g_deg[i] : 0;

    // intra-block inclusive scan
    int x = v;
    #pragma unroll
    for (int d = 1; d < 32; d <<= 1) {
        int y = __shfl_up_sync(0xffffffffu, x, d);
        if ((tid & 31) >= d) x += y;
    }
    if ((tid & 31) == 31) warp_sums[tid >> 5] = x;
    __syncthreads();
    if (tid < 8) {
        int y = warp_sums[tid];
        #pragma unroll
        for (int d = 1; d < 8; d <<= 1) {
            int z = __shfl_up_sync(0xffu, y, d);
            if (tid >= d) y += z;
        }
        warp_sums[tid] = y;
    }
    __syncthreads();
    int incl = x + ((tid >= 32) ? warp_sums[(tid >> 5) - 1] : 0);

    // publish block total (+1 sentinel)
    if (tid == 255) atomicExch(&g_scanv[bid], incl + 1);

    // gather exclusive prefix: spin on predecessors
    int p = 0;
    for (int j = tid; j < bid; j += 256) {
        int val;
        do { val = atomicAdd(&g_scanv[j], 0); } while (val == 0);
        p += val - 1;
    }
    #pragma unroll
    for (int d = 16; d; d >>= 1) p += __shfl_down_sync(0xffffffffu, p, d);
    if ((tid & 31) == 0) red[tid >> 5] = p;
    __syncthreads();
    if (tid == 0) {
        int t = 0;
        #pragma unroll
        for (int w = 0; w < 8; w++) t += red[w];
        s_prefix = t;
    }
    __syncthreads();

    int excl = incl - v + s_prefix;
    if (i < NN) {
        g_offs[i] = excl;
        g_cursor[i] = excl;
        g_dinv[i] = rsqrtf((float)v + 1.0f);
    }
    if (bid == 0 && tid == 0) g_offs[NN] = ne;
}

// ---------------- CSR scatter with fused edge weight ---------------------------
__global__ void k_scatter(const int* __restrict__ src,
                          const int* __restrict__ dst, int ne) {
    int i = blockIdx.x * blockDim.x + threadIdx.x;
    if (i < ne) {
        int d = dst[i];
        int sN = src[i];
        float w = g_dinv[d] * g_dinv[sN];
        int pos = atomicAdd(&g_cursor[d], 1);
        __stcs(&g_edge[pos], make_float2(__int_as_float(sN), w));
    }
}

// ---------------- aggregation core: 2 warps/node, 8-wide fp16 gathers ----------
template <bool POST>
__device__ __forceinline__ void agg_body(const __half* __restrict__ hh,
                                         const float* __restrict__ bias,
                                         __half* __restrict__ outh,
                                         float* __restrict__ outf) {
    int gwarp = (blockIdx.x * blockDim.x + threadIdx.x) >> 5;
    int node = gwarp >> 1;
    if (node >= NN) return;
    int half_ = gwarp & 1;
    int lane = threadIdx.x & 31;
    int coff = half_ * 64 + lane * 2;
    int s = g_offs[node], e = g_offs[node + 1];

    const __half* hb = hh + coff;
    float2 acc0 = make_float2(0.f, 0.f);
    float2 acc1 = make_float2(0.f, 0.f);

    for (int j = s; j < e; j += 8) {
        float2 ed[8];
        #pragma unroll
        for (int u = 0; u < 8; u++) {
            int jj = (j + u < e) ? j + u : e - 1;
            ed[u] = __ldcs(&g_edge[jj]);
            if (j + u >= e) ed[u].y = 0.f;
        }
        uint32_t q[8];
        #pragma unroll
        for (int u = 0; u < 8; u++)
            q[u] = *(const uint32_t*)(hb + (size_t)__float_as_int(ed[u].x) * FD);
        #pragma unroll
        for (int u = 0; u < 8; u += 2) {
            float2 a = __half22float2(*(const __half2*)&q[u]);
            float2 b = __half22float2(*(const __half2*)&q[u + 1]);
            acc0.x = fmaf(ed[u].y, a.x, acc0.x);
            acc0.y = fmaf(ed[u].y, a.y, acc0.y);
            acc1.x = fmaf(ed[u + 1].y, b.x, acc1.x);
            acc1.y = fmaf(ed[u + 1].y, b.y, acc1.y);
        }
    }
    {   // self loop
        float di = g_dinv[node];
        float w = di * di;
        float2 v = __half22float2(*(const __half2*)(hb + (size_t)node * FD));
        acc0.x = fmaf(w, v.x, acc0.x);
        acc0.y = fmaf(w, v.y, acc0.y);
    }
    float2 r = make_float2(acc0.x + acc1.x, acc0.y + acc1.y);
    if (POST) {
        float2 bv = *(const float2*)(bias + coff);
        r.x = fmaxf(r.x + bv.x, 0.f);
        r.y = fmaxf(r.y + bv.y, 0.f);
        __stcs((float2*)(outf + (size_t)node * FD + coff), r);
    } else {
        *(__half2*)(outh + (size_t)node * FD + coff) = __float22half2_rn(r);
    }
}

__global__ void k_agg_pre(const __half* __restrict__ hh, __half* __restrict__ outh) {
    agg_body<false>(hh, nullptr, outh, nullptr);
}

__global__ void k_agg_post(const __half* __restrict__ hh, const float* __restrict__ bias,
                           float* __restrict__ outf) {
    agg_body<true>(hh, bias, nullptr, outf);
}

// ---------------- fp16 tensor-core GEMM: C[n,128] = A[n,128] @ W[128,128] ------
// A fp16 (double-buffered k=32 chunks via cp.async), W fp16 transposed in smem.
// Optional bias+relu epilogue. Output fp16.
#define WT_STRIDE 136                       // halfs; Wt[n][k]
#define AS_STRIDE_H 56                      // halfs; 112B rows (16B-mult, conflict-free)
#define A_CHUNK_HALFS (128 * AS_STRIDE_H)   // 7168
#define GEMM_SMEM ((128 * WT_STRIDE + 2 * A_CHUNK_HALFS) * 2)   // 63,488 B

__global__ __launch_bounds__(256, 2) void k_gemm_f16(const __half* __restrict__ A,
                                                     const float* __restrict__ W,
                                                     const float* __restrict__ bias,
                                                     __half* __restrict__ Ch, int nrows) {
    extern __shared__ __half smh[];
    __half* Wt = smh;                         // [128 n][136 k]
    __half* As = smh + 128 * WT_STRIDE;       // [2][128][56]

    int tid = threadIdx.x;
    int row0 = blockIdx.x * 128;
    uint32_t as_base = (uint32_t)__cvta_generic_to_shared(As);

    // stage W transposed + fp16 (one-time)
    for (int i = tid; i < 128 * 32; i += 256) {
        int r = i >> 5, c = (i & 31) * 4;
        float4 v = ((const float4*)(W + (size_t)r * FD))[i & 31];
        Wt[(c + 0) * WT_STRIDE + r] = __float2half(v.x);
        Wt[(c + 1) * WT_STRIDE + r] = __float2half(v.y);
        Wt[(c + 2) * WT_STRIDE + r] = __float2half(v.z);
        Wt[(c + 3) * WT_STRIDE + r] = __float2half(v.w);
    }

    // A chunk loader: chunk c = k 32c..32c+31 (64B per row), 16B copies
    auto load_chunk = [&](int c, int buf) {
        #pragma unroll
        for (int i = 0; i < 2; i++) {
            int idx = tid + i * 256;          // 0..511
            int r = idx >> 2;                 // 0..127
            int q = idx & 3;                  // 16B quad within 64B
            const __half* g = A + (size_t)(row0 + r) * FD + c * 32 + q * 8;
            uint32_t s = as_base + (uint32_t)(buf * A_CHUNK_HALFS + r * AS_STRIDE_H + q * 8) * 2;
            cp_async16(s, g, (row0 + r < nrows) ? 16 : 0);
        }
    };

    int lane = tid & 31;
    int wid  = tid >> 5;
    int wr = wid & 3;
    int wc = wid >> 2;
    int qrow = lane >> 2;
    int qcol = lane & 3;

    float acc[2][8][4];
    #pragma unroll
    for (int s = 0; s < 2; s++)
        #pragma unroll
        for (int t = 0; t < 8; t++)
            #pragma unroll
            for (int q = 0; q < 4; q++) acc[s][t][q] = 0.f;

    load_chunk(0, 0);
    asm volatile("cp.async.commit_group;" ::: "memory");

    #pragma unroll
    for (int c = 0; c < 4; c++) {
        int buf = c & 1;
        if (c < 3) {
            load_chunk(c + 1, buf ^ 1);
            asm volatile("cp.async.commit_group;" ::: "memory");
            asm volatile("cp.async.wait_group 1;" ::: "memory");
        } else {
            asm volatile("cp.async.wait_group 0;" ::: "memory");
        }
        __syncthreads();

        const __half* Ab = As + buf * A_CHUNK_HALFS;
        #pragma unroll
        for (int ks = 0; ks < 2; ks++) {      // two k16 steps per chunk
            int k0 = ks * 16;
            int K0 = c * 32 + k0;
            uint32_t a[2][4];
            #pragma unroll
            for (int s = 0; s < 2; s++) {
                int rb = 32 * wr + 16 * s + qrow;
                a[s][0] = *(const uint32_t*)&Ab[(rb)     * AS_STRIDE_H + k0 + 2 * qcol];
                a[s][1] = *(const uint32_t*)&Ab[(rb + 8) * AS_STRIDE_H + k0 + 2 * qcol];
                a[s][2] = *(const uint32_t*)&Ab[(rb)     * AS_STRIDE_H + k0 + 2 * qcol + 8];
                a[s][3] = *(const uint32_t*)&Ab[(rb + 8) * AS_STRIDE_H + k0 + 2 * qcol + 8];
            }
            #pragma unroll
            for (int t = 0; t < 8; t++) {
                int n = 64 * wc + 8 * t + qrow;
                uint32_t b0 = *(const uint32_t*)&Wt[n * WT_STRIDE + K0 + 2 * qcol];
                uint32_t b1 = *(const uint32_t*)&Wt[n * WT_STRIDE + K0 + 2 * qcol + 8];
                mma_f16(acc[0][t], a[0], b0, b1);
                mma_f16(acc[1][t], a[1], b0, b1);
            }
        }
        __syncthreads();
    }

    bool has_bias = (bias != nullptr);
    #pragma unroll
    for (int s = 0; s < 2; s++) {
        int rbase = row0 + 32 * wr + 16 * s + qrow;
        #pragma unroll
        for (int t = 0; t < 8; t++) {
            int col = 64 * wc + 8 * t + 2 * qcol;
            float2 lo = make_float2(acc[s][t][0], acc[s][t][1]);
            float2 hi = make_float2(acc[s][t][2], acc[s][t][3]);
            if (has_bias) {
                float b0 = bias[col], b1 = bias[col + 1];
                lo.x = fmaxf(lo.x + b0, 0.f); lo.y = fmaxf(lo.y + b1, 0.f);
                hi.x = fmaxf(hi.x + b0, 0.f); hi.y = fmaxf(hi.y + b1, 0.f);
            }
            if (rbase < nrows)
                *(__half2*)(Ch + (size_t)rbase * FD + col) = __float22half2_rn(lo);
            if (rbase + 8 < nrows)
                *(__half2*)(Ch + (size_t)(rbase + 8) * FD + col) = __float22half2_rn(hi);
        }
    }
}

// ---------------- per-graph mean pool: 1024 thr/graph, 8 row-stripes ------------
__global__ void k_pool(const float* __restrict__ h, const int* __restrict__ bat) {
    int g = blockIdx.x;
    __shared__ int se[2];
    __shared__ float part[7][FD];
    if (threadIdx.x < 2) {
        int target = g + threadIdx.x;
        int lo = 0, hi = NN;
        while (lo < hi) { int m = (lo + hi) >> 1; if (bat[m] < target) lo = m + 1; else hi = m; }
        se[threadIdx.x] = lo;
    }
    __syncthreads();
    int s = se[0], e = se[1];
    int c = threadIdx.x & 127;
    int r0 = threadIdx.x >> 7;
    float acc = 0.f;
    for (int i = s + r0; i < e; i += 8)
        acc += h[(size_t)i * FD + c];
    if (r0 > 0) part[r0 - 1][c] = acc;
    __syncthreads();
    if (r0 == 0) {
        #pragma unroll
        for (int u = 0; u < 7; u++) acc += part[u][c];
        float cnt = (float)((e - s) > 1 ? (e - s) : 1);
        g_pooled[g * FD + c] = acc / cnt;
    }
}

// ---------------- final FC -------------------------------------------------------
__global__ void k_fc(const float* __restrict__ fcW, const float* __restrict__ fcb,
                     float* __restrict__ out) {
    int g = blockIdx.x;
    int c = threadIdx.x;
    float acc = fcb[c];
    #pragma unroll 4
    for (int k = 0; k < FD; k++)
        acc = fmaf(g_pooled[g * FD + k], fcW[k * NC + c], acc);
    out[g * NC + c] = acc;
}

// ---------------- cleanup: restore zero g_deg for next replay -------------------
__global__ void k_cleanup() {
    int i = blockIdx.x * blockDim.x + threadIdx.x;
    if (i < NN) g_deg[i] = 0;
}

// ---------------- launch ----------------------------------------------------------
extern "C" void kernel_launch(void* const* d_in, const int* in_sizes, int n_in,
                              void* d_out, int out_size) {
    const float* x    = (const float*)d_in[0];
    const int*   ei   = (const int*)d_in[1];
    const int*   bat  = (const int*)d_in[2];
    const float* W1   = (const float*)d_in[3];
    const float* b1   = (const float*)d_in[4];
    const float* W2   = (const float*)d_in[5];
    const float* b2   = (const float*)d_in[6];
    const float* fcW  = (const float*)d_in[7];
    const float* fcb  = (const float*)d_in[8];
    float* out = (float*)d_out;

    int ne = in_sizes[1] / 2;
    const int* src = ei;
    const int* dst = ei + ne;

    float *bufB;
    __half *xh, *aggh, *h1h;
    cudaGetSymbolAddress((void**)&bufB, g_bufB);
    cudaGetSymbolAddress((void**)&xh, g_xh);
    cudaGetSymbolAddress((void**)&aggh, g_aggh);
    cudaGetSymbolAddress((void**)&h1h, g_h1h);

    cudaFuncSetAttribute(k_gemm_f16, cudaFuncAttributeMaxDynamicSharedMemorySize, GEMM_SMEM);

    int tb = 256;
    int gbN   = (NN + tb - 1) / tb;
    int gbE   = (ne + tb - 1) / tb;
    int gbAgg = (NN * 2 * 32 + tb - 1) / tb;    // 2 warps per node
    int gbGemm = (NN + 127) / 128;

    k_deg_x2h<<<gbE, tb>>>(dst, ne, x);                               // 0
    k_scan<<<NBLK, tb>>>(ne);                                         // 1
    k_scatter<<<gbE, tb>>>(src, dst, ne);                             // 2
    k_agg_pre<<<gbAgg, tb>>>(xh, aggh);                               // 3 <- profiled
    k_gemm_f16<<<gbGemm, tb, GEMM_SMEM>>>(aggh, W1, b1, h1h, NN);     // 4 (bias+relu)
    k_gemm_f16<<<gbGemm, tb, GEMM_SMEM>>>(h1h, W2, nullptr, aggh, NN);// 5 (plain)
    k_agg_post<<<gbAgg, tb>>>(aggh, b2, bufB);                        // 6 (bias+relu)
    k_pool<<<NG, 1024>>>(bufB, bat);                                  // 7
    k_fc<<<NG, NC>>>(fcW, fcb, out);                                  // 8
    k_cleanup<<<gbN, tb>>>();                                         // 9
}

// round 14
// speedup vs baseline: 1.4459x; 1.0074x over previous
#include <cuda_runtime.h>
#include <cuda_fp16.h>
#include <cstdint>

#define NN 100000
#define NE 1600000
#define FD 128
#define NG 64
#define NC 32

#define NBLK ((NN + 255) / 256)        // 391 scan blocks
#define NEPAD (NE + 8 * NN)            // padded edge capacity

// ---------------- scratch (static device globals; allocation-free) ----------
// g_deg zero at start (static init; re-zeroed by k_cleanup). g_scanv re-zeroed
// by k_deg_x2h before every k_scan (same-stream ordering), replay-safe.
__device__ int    g_deg[NN];
__device__ int    g_offs[NN + 1];
__device__ int    g_cursor[NN];
__device__ float2 g_edge[NEPAD];       // (.x = bitcast(src*FD), .y = weight)
__device__ float  g_dinv[NN];
__device__ int    g_scanv[NBLK];
__device__ __half g_xh[(size_t)NN * FD];      // fp16 X
__device__ __half g_aggh[(size_t)NN * FD];    // agg1 out / gemm2 out (reused)
__device__ __half g_h1h[(size_t)NN * FD];     // gemm1 out (relu'd h1)
__device__ float  g_bufB[(size_t)NN * FD];    // agg2 out fp32
__device__ float  g_pooled[NG * FD];

// ---------------- helpers -----------------------------------------------------
__device__ __forceinline__ void mma_f16(float* d, const uint32_t* a, uint32_t b0, uint32_t b1) {
    asm volatile("mma.sync.aligned.m16n8k16.row.col.f32.f16.f16.f32 "
                 "{%0,%1,%2,%3}, {%4,%5,%6,%7}, {%8,%9}, {%0,%1,%2,%3};"
                 : "+f"(d[0]), "+f"(d[1]), "+f"(d[2]), "+f"(d[3])
                 : "r"(a[0]), "r"(a[1]), "r"(a[2]), "r"(a[3]), "r"(b0), "r"(b1));
}

__device__ __forceinline__ void cp_async16(uint32_t saddr, const void* gptr, int src_bytes) {
    asm volatile("cp.async.ca.shared.global [%0], [%1], 16, %2;"
                 :: "r"(saddr), "l"(gptr), "r"(src_bytes));
}

// ---------------- deg histogram + x->fp16 + scan-flag reset --------------------
__global__ void k_deg_x2h(const int* __restrict__ dst, int ne,
                          const float* __restrict__ x) {
    int gid = blockIdx.x * blockDim.x + threadIdx.x;
    int stride = gridDim.x * blockDim.x;
    if (gid < ne) atomicAdd(&g_deg[dst[gid]], 1);
    if (gid < NBLK) g_scanv[gid] = 0;
    for (int i = gid; i < NN * FD / 2; i += stride) {
        float2 v = ((const float2*)x)[i];
        ((__half2*)g_xh)[i] = __float22half2_rn(v);
    }
}

// ---------------- single-kernel scan over PADDED degrees + pad fill ------------
__global__ void k_scan() {
    __shared__ int warp_sums[8];
    __shared__ int red[8];
    __shared__ int s_prefix;
    int tid = threadIdx.x, bid = blockIdx.x;
    int i = bid * 256 + tid;
    int v  = (i < NN) ? g_deg[i] : 0;
    int vp = (v + 7) & ~7;                 // padded degree

    // intra-block inclusive scan of vp
    int x = vp;
    #pragma unroll
    for (int d = 1; d < 32; d <<= 1) {
        int y = __shfl_up_sync(0xffffffffu, x, d);
        if ((tid & 31) >= d) x += y;
    }
    if ((tid & 31) == 31) warp_sums[tid >> 5] = x;
    __syncthreads();
    if (tid < 8) {
        int y = warp_sums[tid];
        #pragma unroll
        for (int d = 1; d < 8; d <<= 1) {
            int z = __shfl_up_sync(0xffu, y, d);
            if (tid >= d) y += z;
        }
        warp_sums[tid] = y;
    }
    __syncthreads();
    int incl = x + ((tid >= 32) ? warp_sums[(tid >> 5) - 1] : 0);

    if (tid == 255) atomicExch(&g_scanv[bid], incl + 1);   // publish (+1 sentinel)

    // exclusive prefix over predecessor blocks (spin)
    int p = 0;
    for (int j = tid; j < bid; j += 256) {
        int val;
        do { val = atomicAdd(&g_scanv[j], 0); } while (val == 0);
        p += val - 1;
    }
    #pragma unroll
    for (int d = 16; d; d >>= 1) p += __shfl_down_sync(0xffffffffu, p, d);
    if ((tid & 31) == 0) red[tid >> 5] = p;
    __syncthreads();
    if (tid == 0) {
        int t = 0;
        #pragma unroll
        for (int w = 0; w < 8; w++) t += red[w];
        s_prefix = t;
    }
    __syncthreads();

    int excl = incl - vp + s_prefix;
    if (i < NN) {
        g_offs[i] = excl;
        g_cursor[i] = excl;
        g_dinv[i] = rsqrtf((float)v + 1.0f);
        // fill pad slots with weight-0 self records
        float2 padrec = make_float2(__int_as_float(i * FD), 0.f);
        for (int j = v; j < vp; j++) g_edge[excl + j] = padrec;
        if (i == NN - 1) g_offs[NN] = excl + vp;
    }
}

// ---------------- CSR scatter: store (src*FD, weight) --------------------------
__global__ void k_scatter(const int* __restrict__ src,
                          const int* __restrict__ dst, int ne) {
    int i = blockIdx.x * blockDim.x + threadIdx.x;
    if (i < ne) {
        int d = dst[i];
        int sN = src[i];
        float w = g_dinv[d] * g_dinv[sN];
        int pos = atomicAdd(&g_cursor[d], 1);
        __stcs(&g_edge[pos], make_float2(__int_as_float(sN * FD), w));
    }
}

// ---------------- aggregation: 2 warps/node, padded 8-wide, no clamps ----------
template <bool POST>
__device__ __forceinline__ void agg_body(const __half* __restrict__ hh,
                                         const float* __restrict__ bias,
                                         __half* __restrict__ outh,
                                         float* __restrict__ outf) {
    int gwarp = (blockIdx.x * blockDim.x + threadIdx.x) >> 5;
    int node = gwarp >> 1;
    if (node >= NN) return;
    int half_ = gwarp & 1;
    int lane = threadIdx.x & 31;
    int coff = half_ * 64 + lane * 2;
    int s = g_offs[node], e = g_offs[node + 1];   // e-s multiple of 8

    const __half* hb = hh + coff;
    float2 acc0 = make_float2(0.f, 0.f);
    float2 acc1 = make_float2(0.f, 0.f);

    for (int j = s; j < e; j += 8) {
        float2 ed[8];
        #pragma unroll
        for (int u = 0; u < 8; u++) ed[u] = __ldcs(&g_edge[j + u]);
        uint32_t q[8];
        #pragma unroll
        for (int u = 0; u < 8; u++)
            q[u] = *(const uint32_t*)(hb + __float_as_int(ed[u].x));
        #pragma unroll
        for (int u = 0; u < 8; u += 2) {
            float2 a = __half22float2(*(const __half2*)&q[u]);
            float2 b = __half22float2(*(const __half2*)&q[u + 1]);
            acc0.x = fmaf(ed[u].y, a.x, acc0.x);
            acc0.y = fmaf(ed[u].y, a.y, acc0.y);
            acc1.x = fmaf(ed[u + 1].y, b.x, acc1.x);
            acc1.y = fmaf(ed[u + 1].y, b.y, acc1.y);
        }
    }
    {   // self loop
        float di = g_dinv[node];
        float w = di * di;
        float2 v = __half22float2(*(const __half2*)(hb + node * FD));
        acc0.x = fmaf(w, v.x, acc0.x);
        acc0.y = fmaf(w, v.y, acc0.y);
    }
    float2 r = make_float2(acc0.x + acc1.x, acc0.y + acc1.y);
    if (POST) {
        float2 bv = *(const float2*)(bias + coff);
        r.x = fmaxf(r.x + bv.x, 0.f);
        r.y = fmaxf(r.y + bv.y, 0.f);
        __stcs((float2*)(outf + (size_t)node * FD + coff), r);
    } else {
        *(__half2*)(outh + (size_t)node * FD + coff) = __float22half2_rn(r);
    }
}

__global__ void k_agg_pre(const __half* __restrict__ hh, __half* __restrict__ outh) {
    agg_body<false>(hh, nullptr, outh, nullptr);
}

__global__ void k_agg_post(const __half* __restrict__ hh, const float* __restrict__ bias,
                           float* __restrict__ outf) {
    agg_body<true>(hh, bias, nullptr, outf);
}

// ---------------- fp16 tensor-core GEMM: C[n,128] = A[n,128] @ W[128,128] ------
#define WT_STRIDE 136                       // halfs; Wt[n][k]
#define AS_STRIDE_H 56                      // halfs; 112B rows
#define A_CHUNK_HALFS (128 * AS_STRIDE_H)   // 7168
#define GEMM_SMEM ((128 * WT_STRIDE + 2 * A_CHUNK_HALFS) * 2)   // 63,488 B

__global__ __launch_bounds__(256, 2) void k_gemm_f16(const __half* __restrict__ A,
                                                     const float* __restrict__ W,
                                                     const float* __restrict__ bias,
                                                     __half* __restrict__ Ch, int nrows) {
    extern __shared__ __half smh[];
    __half* Wt = smh;                         // [128 n][136 k]
    __half* As = smh + 128 * WT_STRIDE;       // [2][128][56]

    int tid = threadIdx.x;
    int row0 = blockIdx.x * 128;
    uint32_t as_base = (uint32_t)__cvta_generic_to_shared(As);

    for (int i = tid; i < 128 * 32; i += 256) {
        int r = i >> 5, c = (i & 31) * 4;
        float4 v = ((const float4*)(W + (size_t)r * FD))[i & 31];
        Wt[(c + 0) * WT_STRIDE + r] = __float2half(v.x);
        Wt[(c + 1) * WT_STRIDE + r] = __float2half(v.y);
        Wt[(c + 2) * WT_STRIDE + r] = __float2half(v.z);
        Wt[(c + 3) * WT_STRIDE + r] = __float2half(v.w);
    }

    auto load_chunk = [&](int c, int buf) {
        #pragma unroll
        for (int i = 0; i < 2; i++) {
            int idx = tid + i * 256;
            int r = idx >> 2;
            int q = idx & 3;
            const __half* g = A + (size_t)(row0 + r) * FD + c * 32 + q * 8;
            uint32_t s = as_base + (uint32_t)(buf * A_CHUNK_HALFS + r * AS_STRIDE_H + q * 8) * 2;
            cp_async16(s, g, (row0 + r < nrows) ? 16 : 0);
        }
    };

    int lane = tid & 31;
    int wid  = tid >> 5;
    int wr = wid & 3;
    int wc = wid >> 2;
    int qrow = lane >> 2;
    int qcol = lane & 3;

    float acc[2][8][4];
    #pragma unroll
    for (int s = 0; s < 2; s++)
        #pragma unroll
        for (int t = 0; t < 8; t++)
            #pragma unroll
            for (int q = 0; q < 4; q++) acc[s][t][q] = 0.f;

    load_chunk(0, 0);
    asm volatile("cp.async.commit_group;" ::: "memory");

    #pragma unroll
    for (int c = 0; c < 4; c++) {
        int buf = c & 1;
        if (c < 3) {
            load_chunk(c + 1, buf ^ 1);
            asm volatile("cp.async.commit_group;" ::: "memory");
            asm volatile("cp.async.wait_group 1;" ::: "memory");
        } else {
            asm volatile("cp.async.wait_group 0;" ::: "memory");
        }
        __syncthreads();

        const __half* Ab = As + buf * A_CHUNK_HALFS;
        #pragma unroll
        for (int ks = 0; ks < 2; ks++) {
            int k0 = ks * 16;
            int K0 = c * 32 + k0;
            uint32_t a[2][4];
            #pragma unroll
            for (int s = 0; s < 2; s++) {
                int rb = 32 * wr + 16 * s + qrow;
                a[s][0] = *(const uint32_t*)&Ab[(rb)     * AS_STRIDE_H + k0 + 2 * qcol];
                a[s][1] = *(const uint32_t*)&Ab[(rb + 8) * AS_STRIDE_H + k0 + 2 * qcol];
                a[s][2] = *(const uint32_t*)&Ab[(rb)     * AS_STRIDE_H + k0 + 2 * qcol + 8];
                a[s][3] = *(const uint32_t*)&Ab[(rb + 8) * AS_STRIDE_H + k0 + 2 * qcol + 8];
            }
            #pragma unroll
            for (int t = 0; t < 8; t++) {
                int n = 64 * wc + 8 * t + qrow;
                uint32_t b0 = *(const uint32_t*)&Wt[n * WT_STRIDE + K0 + 2 * qcol];
                uint32_t b1 = *(const uint32_t*)&Wt[n * WT_STRIDE + K0 + 2 * qcol + 8];
                mma_f16(acc[0][t], a[0], b0, b1);
                mma_f16(acc[1][t], a[1], b0, b1);
            }
        }
        __syncthreads();
    }

    bool has_bias = (bias != nullptr);
    #pragma unroll
    for (int s = 0; s < 2; s++) {
        int rbase = row0 + 32 * wr + 16 * s + qrow;
        #pragma unroll
        for (int t = 0; t < 8; t++) {
            int col = 64 * wc + 8 * t + 2 * qcol;
            float2 lo = make_float2(acc[s][t][0], acc[s][t][1]);
            float2 hi = make_float2(acc[s][t][2], acc[s][t][3]);
            if (has_bias) {
                float b0 = bias[col], b1 = bias[col + 1];
                lo.x = fmaxf(lo.x + b0, 0.f); lo.y = fmaxf(lo.y + b1, 0.f);
                hi.x = fmaxf(hi.x + b0, 0.f); hi.y = fmaxf(hi.y + b1, 0.f);
            }
            if (rbase < nrows)
                *(__half2*)(Ch + (size_t)rbase * FD + col) = __float22half2_rn(lo);
            if (rbase + 8 < nrows)
                *(__half2*)(Ch + (size_t)(rbase + 8) * FD + col) = __float22half2_rn(hi);
        }
    }
}

// ---------------- per-graph mean pool: 1024 thr/graph, 8 row-stripes ------------
__global__ void k_pool(const float* __restrict__ h, const int* __restrict__ bat) {
    int g = blockIdx.x;
    __shared__ int se[2];
    __shared__ float part[7][FD];
    if (threadIdx.x < 2) {
        int target = g + threadIdx.x;
        int lo = 0, hi = NN;
        while (lo < hi) { int m = (lo + hi) >> 1; if (bat[m] < target) lo = m + 1; else hi = m; }
        se[threadIdx.x] = lo;
    }
    __syncthreads();
    int s = se[0], e = se[1];
    int c = threadIdx.x & 127;
    int r0 = threadIdx.x >> 7;
    float acc = 0.f;
    for (int i = s + r0; i < e; i += 8)
        acc += h[(size_t)i * FD + c];
    if (r0 > 0) part[r0 - 1][c] = acc;
    __syncthreads();
    if (r0 == 0) {
        #pragma unroll
        for (int u = 0; u < 7; u++) acc += part[u][c];
        float cnt = (float)((e - s) > 1 ? (e - s) : 1);
        g_pooled[g * FD + c] = acc / cnt;
    }
}

// ---------------- final FC -------------------------------------------------------
__global__ void k_fc(const float* __restrict__ fcW, const float* __restrict__ fcb,
                     float* __restrict__ out) {
    int g = blockIdx.x;
    int c = threadIdx.x;
    float acc = fcb[c];
    #pragma unroll 4
    for (int k = 0; k < FD; k++)
        acc = fmaf(g_pooled[g * FD + k], fcW[k * NC + c], acc);
    out[g * NC + c] = acc;
}

// ---------------- cleanup: restore zero g_deg for next replay -------------------
__global__ void k_cleanup() {
    int i = blockIdx.x * blockDim.x + threadIdx.x;
    if (i < NN) g_deg[i] = 0;
}

// ---------------- launch ----------------------------------------------------------
extern "C" void kernel_launch(void* const* d_in, const int* in_sizes, int n_in,
                              void* d_out, int out_size) {
    const float* x    = (const float*)d_in[0];
    const int*   ei   = (const int*)d_in[1];
    const int*   bat  = (const int*)d_in[2];
    const float* W1   = (const float*)d_in[3];
    const float* b1   = (const float*)d_in[4];
    const float* W2   = (const float*)d_in[5];
    const float* b2   = (const float*)d_in[6];
    const float* fcW  = (const float*)d_in[7];
    const float* fcb  = (const float*)d_in[8];
    float* out = (float*)d_out;

    int ne = in_sizes[1] / 2;
    const int* src = ei;
    const int* dst = ei + ne;

    float *bufB;
    __half *xh, *aggh, *h1h;
    cudaGetSymbolAddress((void**)&bufB, g_bufB);
    cudaGetSymbolAddress((void**)&xh, g_xh);
    cudaGetSymbolAddress((void**)&aggh, g_aggh);
    cudaGetSymbolAddress((void**)&h1h, g_h1h);

    cudaFuncSetAttribute(k_gemm_f16, cudaFuncAttributeMaxDynamicSharedMemorySize, GEMM_SMEM);

    int tb = 256;
    int gbN   = (NN + tb - 1) / tb;
    int gbE   = (ne + tb - 1) / tb;
    int gbAgg = (NN * 2 * 32 + tb - 1) / tb;    // 2 warps per node
    int gbGemm = (NN + 127) / 128;

    k_deg_x2h<<<gbE, tb>>>(dst, ne, x);                               // 0
    k_scan<<<NBLK, tb>>>();                                           // 1 (+pad fill)
    k_scatter<<<gbE, tb>>>(src, dst, ne);                             // 2
    k_agg_pre<<<gbAgg, tb>>>(xh, aggh);                               // 3 <- profiled
    k_gemm_f16<<<gbGemm, tb, GEMM_SMEM>>>(aggh, W1, b1, h1h, NN);     // 4 (bias+relu)
    k_gemm_f16<<<gbGemm, tb, GEMM_SMEM>>>(h1h, W2, nullptr, aggh, NN);// 5 (plain)
    k_agg_post<<<gbAgg, tb>>>(aggh, b2, bufB);                        // 6 (bias+relu)
    k_pool<<<NG, 1024>>>(bufB, bat);                                  // 7
    k_fc<<<NG, NC>>>(fcW, fcb, out);                                  // 8
    k_cleanup<<<gbN, tb>>>();                                         // 9
}